// round 9
// baseline (speedup 1.0000x reference)
#include <cuda_runtime.h>
#include <cstdint>

#define Bx   4
#define Sx   1024
#define Hx   8
#define Dx   64
#define HDx  512
#define EMBx 512
#define XLx  1024
#define Jx   2048
#define KKx  32

// ---------------- device scratch ----------------
__device__ float g_q[Bx * Hx * Sx * Dx];     // exact (knn reads it)
__device__ float g_k[Bx * Hx * Jx * Dx];     // tf32-rounded at producer
__device__ float g_v[Bx * Hx * Jx * Dx];     // tf32-rounded at producer
__device__ float g_loc[Bx * Hx * Sx * Dx];   // g * local attn out
__device__ float g_ext[Bx * Sx * HDx];       // (1-g) * knn out

// ---------------- helpers ----------------
__device__ __forceinline__ float tf32r(float x) {
    uint32_t u;
    asm("cvt.rna.tf32.f32 %0, %1;" : "=r"(u) : "f"(x));
    return __uint_as_float(u);
}
__device__ __forceinline__ float4 tf32r4(float4 f) {
    f.x = tf32r(f.x); f.y = tf32r(f.y); f.z = tf32r(f.z); f.w = tf32r(f.w);
    return f;
}
__device__ __forceinline__ void mma_tf32(float* c, const float* a, const float* b)
{
    asm volatile(
        "mma.sync.aligned.m16n8k8.row.col.f32.tf32.tf32.f32 "
        "{%0,%1,%2,%3},{%4,%5,%6,%7},{%8,%9},{%0,%1,%2,%3};\n"
        : "+f"(c[0]), "+f"(c[1]), "+f"(c[2]), "+f"(c[3])
        : "r"(__float_as_uint(a[0])), "r"(__float_as_uint(a[1])),
          "r"(__float_as_uint(a[2])), "r"(__float_as_uint(a[3])),
          "r"(__float_as_uint(b[0])), "r"(__float_as_uint(b[1])));
}

// ===========================================================================
// Fused QKV projection GEMM (+ xl_memory copy blocks).  (round-7 version)
// ===========================================================================
__global__ __launch_bounds__(256) void qkv_gemm(
    const float* __restrict__ x,
    const float* __restrict__ Wq, const float* __restrict__ bq,
    const float* __restrict__ Wk, const float* __restrict__ bk,
    const float* __restrict__ Wv, const float* __restrict__ bv,
    const float* __restrict__ xlm,
    float* __restrict__ kvout)
{
    extern __shared__ float smg[];

    if (blockIdx.x >= 768) {
        int base = (blockIdx.x - 768) * 1024;
#pragma unroll
        for (int i = 0; i < 4; i++) {
            int idx = base + i * 256 + threadIdx.x;
            int n4 = idx & 127;
            int rest = idx >> 7;
            int c = rest & 1;  rest >>= 1;
            int j = rest & 1023;
            int b = rest >> 10;
            float4 f = tf32r4(((const float4*)xlm)[idx]);
            int n = n4 * 4;
            int h = n >> 6, d = n & 63;
            float* dst = (c ? g_v : g_k) + (((size_t)(b * Hx + h)) * Jx + j) * Dx + d;
            *(float4*)dst = f;
        }
        return;
    }

    float* Ab = smg;
    float* Bb = Ab + 128 * 36;
    float* Al = Bb + 64 * 36;
    float* Bl = Al + 128 * 36;

    int bm   = blockIdx.x & 31;
    int nbi  = blockIdx.x >> 5;
    int nsec = nbi >> 3;
    int m0 = bm * 128, n0 = (nbi & 7) * 64;
    bool s3 = (nsec != 0);

    const float* W    = (nsec == 0) ? Wq : (nsec == 1) ? Wk : Wv;
    const float* bias = (nsec == 0) ? bq : (nsec == 1) ? bk : bv;

    int tid = threadIdx.x;
    int wid = tid >> 5, lane = tid & 31;
    int wm = wid & 3, wn = wid >> 2;
    int g = lane >> 2, tig = lane & 3;

    float acc[2][4][4];
#pragma unroll
    for (int i = 0; i < 2; i++)
#pragma unroll
        for (int j = 0; j < 4; j++)
#pragma unroll
            for (int e = 0; e < 4; e++) acc[i][j][e] = 0.f;

    int a_row = tid >> 1;
    int a_c0  = (tid & 1) * 16;
    int b_row = tid >> 2;
    int b_c0  = (tid & 3) * 8;

    const float* Agp = x + (size_t)(m0 + a_row) * 512 + a_c0;
    const float* Wgp = W + (size_t)(n0 + b_row) * 512 + b_c0;

    for (int kc = 0; kc < 16; kc++) {
        int k0 = kc * 32;
        float4 ra[4], rb[2];
#pragma unroll
        for (int i = 0; i < 4; i++) ra[i] = *(const float4*)(Agp + k0 + i * 4);
#pragma unroll
        for (int i = 0; i < 2; i++) rb[i] = *(const float4*)(Wgp + k0 + i * 4);
        __syncthreads();
#pragma unroll
        for (int i = 0; i < 4; i++) {
            float4 f = ra[i];
            float4 bg = tf32r4(f);
            *(float4*)&Ab[a_row * 36 + a_c0 + i * 4] = bg;
            if (s3) {
                float4 sl;
                sl.x = tf32r(f.x - bg.x); sl.y = tf32r(f.y - bg.y);
                sl.z = tf32r(f.z - bg.z); sl.w = tf32r(f.w - bg.w);
                *(float4*)&Al[a_row * 36 + a_c0 + i * 4] = sl;
            }
        }
#pragma unroll
        for (int i = 0; i < 2; i++) {
            float4 f = rb[i];
            float4 bg = tf32r4(f);
            *(float4*)&Bb[b_row * 36 + b_c0 + i * 4] = bg;
            if (s3) {
                float4 sl;
                sl.x = tf32r(f.x - bg.x); sl.y = tf32r(f.y - bg.y);
                sl.z = tf32r(f.z - bg.z); sl.w = tf32r(f.w - bg.w);
                *(float4*)&Bl[b_row * 36 + b_c0 + i * 4] = sl;
            }
        }
        __syncthreads();

#pragma unroll
        for (int kk = 0; kk < 4; kk++) {
            int kb = kk * 8;
            float a[2][4], as[2][4];
#pragma unroll
            for (int mi = 0; mi < 2; mi++) {
                int base = wm * 32 + mi * 16;
                a[mi][0] = Ab[(base + g)     * 36 + kb + tig];
                a[mi][1] = Ab[(base + g + 8) * 36 + kb + tig];
                a[mi][2] = Ab[(base + g)     * 36 + kb + tig + 4];
                a[mi][3] = Ab[(base + g + 8) * 36 + kb + tig + 4];
                if (s3) {
                    as[mi][0] = Al[(base + g)     * 36 + kb + tig];
                    as[mi][1] = Al[(base + g + 8) * 36 + kb + tig];
                    as[mi][2] = Al[(base + g)     * 36 + kb + tig + 4];
                    as[mi][3] = Al[(base + g + 8) * 36 + kb + tig + 4];
                }
            }
            float b[4][2], bs[4][2];
#pragma unroll
            for (int ni = 0; ni < 4; ni++) {
                int nb = wn * 32 + ni * 8;
                b[ni][0] = Bb[(nb + g) * 36 + kb + tig];
                b[ni][1] = Bb[(nb + g) * 36 + kb + tig + 4];
                if (s3) {
                    bs[ni][0] = Bl[(nb + g) * 36 + kb + tig];
                    bs[ni][1] = Bl[(nb + g) * 36 + kb + tig + 4];
                }
            }
#pragma unroll
            for (int mi = 0; mi < 2; mi++)
#pragma unroll
                for (int ni = 0; ni < 4; ni++) {
                    mma_tf32(acc[mi][ni], a[mi], b[ni]);
                    if (s3) {
                        mma_tf32(acc[mi][ni], a[mi], bs[ni]);
                        mma_tf32(acc[mi][ni], as[mi], b[ni]);
                    }
                }
        }
    }

#pragma unroll
    for (int mi = 0; mi < 2; mi++) {
#pragma unroll
        for (int ni = 0; ni < 4; ni++) {
#pragma unroll
            for (int e = 0; e < 4; e++) {
                int m = m0 + wm * 32 + mi * 16 + g + ((e >> 1) * 8);
                int n = n0 + wn * 32 + ni * 8 + tig * 2 + (e & 1);
                float c = acc[mi][ni][e] + bias[n];
                int b = m >> 10, s = m & 1023;
                int h = n >> 6, d = n & 63;
                if (nsec == 0) {
                    g_q[(((size_t)(b * Hx + h)) * Sx + s) * Dx + d] = c;
                } else if (nsec == 1) {
                    g_k[(((size_t)(b * Hx + h)) * Jx + XLx + s) * Dx + d] = tf32r(c);
                    kvout[(((size_t)(b * Sx + s)) * 2 + 0) * HDx + n] = c;
                } else {
                    g_v[(((size_t)(b * Hx + h)) * Jx + XLx + s) * Dx + d] = tf32r(c);
                    kvout[(((size_t)(b * Sx + s)) * 2 + 1) * HDx + n] = c;
                }
            }
        }
    }
}

// ===========================================================================
// Fused attention + kNN, interleaved 16:1. 4352 blocks = 256*17:
//   blockIdx%17==16 : attention block, aid = blockIdx/17 (bh = aid>>3, qt = aid&7)
//   else            : kNN block, kid = blockIdx - blockIdx/17 in [0,4096)
// Attention: 128-query tile, 8 warps = 4 m-warps (32 q each) x 2 key-halves.
// ===========================================================================
__global__ __launch_bounds__(256, 2) void attn_knn(const float* __restrict__ rel,
                                                   const float* __restrict__ gate,
                                                   const float* __restrict__ knn)
{
    extern __shared__ float sm[];
    int tid = threadIdx.x;
    int wid = tid >> 5, lane = tid & 31;

    if (blockIdx.x % 17 != 16) {
        // ------------------- kNN part (coalesced, round-7) -------------------
        int kid = blockIdx.x - blockIdx.x / 17;  // 0..4095
        int b = kid >> 10, s = kid & 1023;
        int h = wid;

        const float* qp = g_q + (((size_t)(b * Hx + h)) * Sx + s) * Dx;
        float2 qv = *(const float2*)(qp + lane * 2);

        const float4* src =
            (const float4*)(knn + ((size_t)(b * Sx + s)) * (KKx * 2 * HDx));
        float4* dstv = (float4*)sm;              // 4096 float4 = 64KB

        float m = -1e30f, l = 0.f, a0 = 0.f, a1 = 0.f;

#pragma unroll
        for (int c = 0; c < 2; c++) {
            __syncthreads();
#pragma unroll
            for (int i = 0; i < 16; i++) {
                int idx = tid + i * 256;
                dstv[idx] = src[c * 4096 + idx];
            }
            __syncthreads();

            float sc[16];
#pragma unroll
            for (int kk = 0; kk < 16; kk++) {
                float2 kf = *(const float2*)(sm + kk * 1024 + h * 64 + lane * 2);
                float p = qv.x * kf.x + qv.y * kf.y;
                p += __shfl_xor_sync(0xffffffffu, p, 16);
                p += __shfl_xor_sync(0xffffffffu, p, 8);
                p += __shfl_xor_sync(0xffffffffu, p, 4);
                p += __shfl_xor_sync(0xffffffffu, p, 2);
                p += __shfl_xor_sync(0xffffffffu, p, 1);
                sc[kk] = p * 0.125f;
            }
            float cm = sc[0];
#pragma unroll
            for (int kk = 1; kk < 16; kk++) cm = fmaxf(cm, sc[kk]);
            float mn = fmaxf(m, cm);
            float al = __expf(m - mn);
            a0 *= al; a1 *= al; l *= al;
#pragma unroll
            for (int kk = 0; kk < 16; kk++) {
                float p = __expf(sc[kk] - mn);
                l += p;
                float2 vf = *(const float2*)(sm + kk * 1024 + 512 + h * 64 + lane * 2);
                a0 = fmaf(p, vf.x, a0);
                a1 = fmaf(p, vf.y, a1);
            }
            m = mn;
        }

        float gg = 1.f / (1.f + __expf(-gate[h]));
        float w = (1.f - gg) / l;
        float2 st; st.x = w * a0; st.y = w * a1;
        *(float2*)&g_ext[((size_t)(b * Sx + s)) * HDx + h * 64 + lane * 2] = st;
        return;
    }

    // ------------------- attention part: 128-q tile -------------------
    float* Qs = sm;                        // [128][68]  (34,816 B)
    float* Ks = Qs + 128 * 68;             // [64][68]
    float* Vs = Ks + 64 * 68;              // [64][68]
    float* Pw = Vs + 64 * 68 + wid * 1152; // per-warp [32][36]

    int aid = blockIdx.x / 17;             // 0..255
    int bh = aid >> 3;
    int h = bh & 7;
    int qt = aid & 7;
    int i0 = qt * 128;
    int wm = wid & 3, wn = wid >> 2;
    int g = lane >> 2, tig = lane & 3;
    int qb = wm * 32;                      // warp's query base within tile

    // load Q tile (tf32-rounded)
    const float* qbase = g_q + (((size_t)bh) * Sx + i0) * Dx;
    for (int idx = tid; idx < 2048; idx += 256) {
        int row = idx >> 4, c4 = idx & 15;
        *(float4*)&Qs[row * 68 + c4 * 4] =
            tf32r4(*(const float4*)(qbase + row * 64 + c4 * 4));
    }

    float o[2][8][4];
#pragma unroll
    for (int mi = 0; mi < 2; mi++)
#pragma unroll
        for (int ni = 0; ni < 8; ni++)
#pragma unroll
            for (int e = 0; e < 4; e++) o[mi][ni][e] = 0.f;
    float mrow[2][2], lrow[2][2];
#pragma unroll
    for (int mi = 0; mi < 2; mi++) {
        mrow[mi][0] = -1e30f; mrow[mi][1] = -1e30f;
        lrow[mi][0] = 0.f;    lrow[mi][1] = 0.f;
    }

    int ntiles = 2 * qt + 18;
    const float* kbase = g_k + ((size_t)bh) * Jx * Dx;
    const float* vbase = g_v + ((size_t)bh) * Jx * Dx;
    const float* relh  = rel + (size_t)h * Sx * Jx;

    for (int t = 0; t < ntiles; t++) {
        int j0 = t * 64;
        __syncthreads();
        for (int idx = tid; idx < 1024; idx += 256) {
            int row = idx >> 4, c4 = idx & 15;
            *(float4*)&Ks[row * 68 + c4 * 4] =
                *(const float4*)(kbase + (size_t)(j0 + row) * 64 + c4 * 4);
            *(float4*)&Vs[row * 68 + c4 * 4] =
                *(const float4*)(vbase + (size_t)(j0 + row) * 64 + c4 * 4);
        }
        __syncthreads();

        bool maskt = (t >= ntiles - 2);
        float al[2][2];

#pragma unroll
        for (int mi = 0; mi < 2; mi++) {
            int rbase = qb + mi * 16;
            int qi0 = i0 + rbase + g, qi1 = qi0 + 8;

            // ---- S = Q K^T over warp's 32-key half ----
            float c[4][4];
#pragma unroll
            for (int ni = 0; ni < 4; ni++)
#pragma unroll
                for (int e = 0; e < 4; e++) c[ni][e] = 0.f;
#pragma unroll
            for (int kk = 0; kk < 8; kk++) {
                int kb = kk * 8;
                float a[4];
                a[0] = Qs[(rbase + g)     * 68 + kb + tig];
                a[1] = Qs[(rbase + g + 8) * 68 + kb + tig];
                a[2] = Qs[(rbase + g)     * 68 + kb + tig + 4];
                a[3] = Qs[(rbase + g + 8) * 68 + kb + tig + 4];
#pragma unroll
                for (int ni = 0; ni < 4; ni++) {
                    int krow = wn * 32 + ni * 8 + g;
                    float b[2];
                    b[0] = Ks[krow * 68 + kb + tig];
                    b[1] = Ks[krow * 68 + kb + tig + 4];
                    mma_tf32(c[ni], a, b);
                }
            }

            // ---- rel_pos + scale (+ causal mask on boundary tiles) ----
            const float* rr0 = relh + (size_t)qi0 * Jx + j0;
            const float* rr1 = relh + (size_t)qi1 * Jx + j0;
            if (maskt) {
#pragma unroll
                for (int ni = 0; ni < 4; ni++) {
                    int kcol = wn * 32 + ni * 8 + tig * 2;
                    int kj = j0 + kcol;
                    float2 rp0 = *(const float2*)(rr0 + kcol);
                    float2 rp1 = *(const float2*)(rr1 + kcol);
                    c[ni][0] = (kj     <= qi0 + XLx) ? (c[ni][0] + rp0.x) * 0.125f : -1e30f;
                    c[ni][1] = (kj + 1 <= qi0 + XLx) ? (c[ni][1] + rp0.y) * 0.125f : -1e30f;
                    c[ni][2] = (kj     <= qi1 + XLx) ? (c[ni][2] + rp1.x) * 0.125f : -1e30f;
                    c[ni][3] = (kj + 1 <= qi1 + XLx) ? (c[ni][3] + rp1.y) * 0.125f : -1e30f;
                }
            } else {
#pragma unroll
                for (int ni = 0; ni < 4; ni++) {
                    int kcol = wn * 32 + ni * 8 + tig * 2;
                    float2 rp0 = *(const float2*)(rr0 + kcol);
                    float2 rp1 = *(const float2*)(rr1 + kcol);
                    c[ni][0] = (c[ni][0] + rp0.x) * 0.125f;
                    c[ni][1] = (c[ni][1] + rp0.y) * 0.125f;
                    c[ni][2] = (c[ni][2] + rp1.x) * 0.125f;
                    c[ni][3] = (c[ni][3] + rp1.y) * 0.125f;
                }
            }

            // ---- warp-private online softmax for this mi ----
            float rm0 = -1e30f, rm1 = -1e30f;
#pragma unroll
            for (int ni = 0; ni < 4; ni++) {
                rm0 = fmaxf(rm0, fmaxf(c[ni][0], c[ni][1]));
                rm1 = fmaxf(rm1, fmaxf(c[ni][2], c[ni][3]));
            }
            rm0 = fmaxf(rm0, __shfl_xor_sync(0xffffffffu, rm0, 1));
            rm0 = fmaxf(rm0, __shfl_xor_sync(0xffffffffu, rm0, 2));
            rm1 = fmaxf(rm1, __shfl_xor_sync(0xffffffffu, rm1, 1));
            rm1 = fmaxf(rm1, __shfl_xor_sync(0xffffffffu, rm1, 2));
            float mn0 = fmaxf(mrow[mi][0], rm0), mn1 = fmaxf(mrow[mi][1], rm1);
            al[mi][0] = __expf(mrow[mi][0] - mn0);
            al[mi][1] = __expf(mrow[mi][1] - mn1);
            float ls0 = 0.f, ls1 = 0.f;
#pragma unroll
            for (int ni = 0; ni < 4; ni++) {
                int kcol = ni * 8 + tig * 2;
                float p00 = tf32r(__expf(c[ni][0] - mn0));
                float p01 = tf32r(__expf(c[ni][1] - mn0));
                float p10 = tf32r(__expf(c[ni][2] - mn1));
                float p11 = tf32r(__expf(c[ni][3] - mn1));
                ls0 += p00 + p01; ls1 += p10 + p11;
                int pr = mi * 16;
                Pw[(pr + g)     * 36 + kcol]     = p00;
                Pw[(pr + g)     * 36 + kcol + 1] = p01;
                Pw[(pr + g + 8) * 36 + kcol]     = p10;
                Pw[(pr + g + 8) * 36 + kcol + 1] = p11;
            }
            ls0 += __shfl_xor_sync(0xffffffffu, ls0, 1);
            ls0 += __shfl_xor_sync(0xffffffffu, ls0, 2);
            ls1 += __shfl_xor_sync(0xffffffffu, ls1, 1);
            ls1 += __shfl_xor_sync(0xffffffffu, ls1, 2);
            lrow[mi][0] = lrow[mi][0] * al[mi][0] + ls0;
            lrow[mi][1] = lrow[mi][1] * al[mi][1] + ls1;
            mrow[mi][0] = mn0; mrow[mi][1] = mn1;
        }

        // rescale accumulators
#pragma unroll
        for (int mi = 0; mi < 2; mi++)
#pragma unroll
            for (int ni = 0; ni < 8; ni++) {
                o[mi][ni][0] *= al[mi][0]; o[mi][ni][1] *= al[mi][0];
                o[mi][ni][2] *= al[mi][1]; o[mi][ni][3] *= al[mi][1];
            }
        __syncwarp();

        // ---- O += P V  (both mi share the V fragments) ----
#pragma unroll
        for (int kk = 0; kk < 4; kk++) {
            int kb = kk * 8;
            float a0[4], a1[4];
            a0[0] = Pw[(g)      * 36 + kb + tig];
            a0[1] = Pw[(g + 8)  * 36 + kb + tig];
            a0[2] = Pw[(g)      * 36 + kb + tig + 4];
            a0[3] = Pw[(g + 8)  * 36 + kb + tig + 4];
            a1[0] = Pw[(g + 16) * 36 + kb + tig];
            a1[1] = Pw[(g + 24) * 36 + kb + tig];
            a1[2] = Pw[(g + 16) * 36 + kb + tig + 4];
            a1[3] = Pw[(g + 24) * 36 + kb + tig + 4];
            int vrow = wn * 32 + kb + tig;
#pragma unroll
            for (int ni = 0; ni < 8; ni++) {
                float b[2];
                b[0] = Vs[vrow * 68 + ni * 8 + g];
                b[1] = Vs[(vrow + 4) * 68 + ni * 8 + g];
                mma_tf32(o[0][ni], a0, b);
                mma_tf32(o[1][ni], a1, b);
            }
        }
    }

    // ---- merge the two key-halves (scratch over Ks+Vs; m/l in Qs) ----
    __syncthreads();
    float* M = Ks;                          // [128][68]
    if (wn == 1) {
#pragma unroll
        for (int mi = 0; mi < 2; mi++) {
            int row0 = qb + mi * 16 + g, row1 = row0 + 8;
#pragma unroll
            for (int ni = 0; ni < 8; ni++) {
                int col = ni * 8 + tig * 2;
                M[row0 * 68 + col]     = o[mi][ni][0];
                M[row0 * 68 + col + 1] = o[mi][ni][1];
                M[row1 * 68 + col]     = o[mi][ni][2];
                M[row1 * 68 + col + 1] = o[mi][ni][3];
            }
            if (tig == 0) {
                Qs[row0] = mrow[mi][0]; Qs[row1] = mrow[mi][1];
                Qs[128 + row0] = lrow[mi][0]; Qs[128 + row1] = lrow[mi][1];
            }
        }
    }
    __syncthreads();
    if (wn == 0) {
        float gsig = 1.f / (1.f + __expf(-gate[h]));
#pragma unroll
        for (int mi = 0; mi < 2; mi++) {
            int row0 = qb + mi * 16 + g, row1 = row0 + 8;
            float mp0 = Qs[row0], mp1 = Qs[row1];
            float lp0 = Qs[128 + row0], lp1 = Qs[128 + row1];
            float mt0 = fmaxf(mrow[mi][0], mp0), mt1 = fmaxf(mrow[mi][1], mp1);
            float a00 = __expf(mrow[mi][0] - mt0), a01 = __expf(mp0 - mt0);
            float a10 = __expf(mrow[mi][1] - mt1), a11 = __expf(mp1 - mt1);
            float inv0 = gsig / (lrow[mi][0] * a00 + lp0 * a01);
            float inv1 = gsig / (lrow[mi][1] * a10 + lp1 * a11);
#pragma unroll
            for (int ni = 0; ni < 8; ni++) {
                int col = ni * 8 + tig * 2;
                float2 s0, s1;
                s0.x = (o[mi][ni][0] * a00 + M[row0 * 68 + col]     * a01) * inv0;
                s0.y = (o[mi][ni][1] * a00 + M[row0 * 68 + col + 1] * a01) * inv0;
                s1.x = (o[mi][ni][2] * a10 + M[row1 * 68 + col]     * a11) * inv1;
                s1.y = (o[mi][ni][3] * a10 + M[row1 * 68 + col + 1] * a11) * inv1;
                *(float2*)&g_loc[(((size_t)bh) * Sx + i0 + row0) * Dx + col] = s0;
                *(float2*)&g_loc[(((size_t)bh) * Sx + i0 + row1) * Dx + col] = s1;
            }
        }
    }
}

// ===========================================================================
// Output projection: out[4096,512] = (g_loc + g_ext) @ Wo^T + bo (3xTF32)
// ===========================================================================
__global__ __launch_bounds__(256) void out_gemm(const float* __restrict__ W,
                                                const float* __restrict__ bias,
                                                float* __restrict__ dst)
{
    extern __shared__ float smg[];
    float* Ab = smg;
    float* Bb = Ab + 128 * 36;
    float* Al = Bb + 64 * 36;
    float* Bl = Al + 128 * 36;

    int tid = threadIdx.x;
    int wid = tid >> 5, lane = tid & 31;
    int wm = wid & 3, wn = wid >> 2;
    int g = lane >> 2, tig = lane & 3;
    int m0 = blockIdx.x * 128, n0 = blockIdx.y * 64;

    float acc[2][4][4];
#pragma unroll
    for (int i = 0; i < 2; i++)
#pragma unroll
        for (int j = 0; j < 4; j++)
#pragma unroll
            for (int e = 0; e < 4; e++) acc[i][j][e] = 0.f;

    int a_row = tid >> 1;
    int a_c0  = (tid & 1) * 16;
    int b_row = tid >> 2;
    int b_c0  = (tid & 3) * 8;

    int mrow = m0 + a_row;
    int ab = mrow >> 10, as_ = mrow & 1023;
    const float* extp = g_ext + (size_t)mrow * 512;
    const float* Wgp = W + (size_t)(n0 + b_row) * 512 + b_c0;

    for (int kc = 0; kc < 16; kc++) {
        int k0 = kc * 32;
        float4 ra[4], rb[2];
#pragma unroll
        for (int i = 0; i < 4; i++) {
            int cc = a_c0 + k0 + i * 4;
            int hh = cc >> 6, dd = cc & 63;
            float4 f1 = *(const float4*)&g_loc[(((size_t)(ab * Hx + hh)) * Sx + as_) * Dx + dd];
            float4 f2 = *(const float4*)(extp + cc);
            ra[i].x = f1.x + f2.x; ra[i].y = f1.y + f2.y;
            ra[i].z = f1.z + f2.z; ra[i].w = f1.w + f2.w;
        }
#pragma unroll
        for (int i = 0; i < 2; i++) rb[i] = *(const float4*)(Wgp + k0 + i * 4);
        __syncthreads();
#pragma unroll
        for (int i = 0; i < 4; i++) {
            float4 f = ra[i];
            float4 bg = tf32r4(f);
            *(float4*)&Ab[a_row * 36 + a_c0 + i * 4] = bg;
            float4 sl;
            sl.x = tf32r(f.x - bg.x); sl.y = tf32r(f.y - bg.y);
            sl.z = tf32r(f.z - bg.z); sl.w = tf32r(f.w - bg.w);
            *(float4*)&Al[a_row * 36 + a_c0 + i * 4] = sl;
        }
#pragma unroll
        for (int i = 0; i < 2; i++) {
            float4 f = rb[i];
            float4 bg = tf32r4(f);
            *(float4*)&Bb[b_row * 36 + b_c0 + i * 4] = bg;
            float4 sl;
            sl.x = tf32r(f.x - bg.x); sl.y = tf32r(f.y - bg.y);
            sl.z = tf32r(f.z - bg.z); sl.w = tf32r(f.w - bg.w);
            *(float4*)&Bl[b_row * 36 + b_c0 + i * 4] = sl;
        }
        __syncthreads();

#pragma unroll
        for (int kk = 0; kk < 4; kk++) {
            int kb = kk * 8;
            float a[2][4], asr[2][4];
#pragma unroll
            for (int mi = 0; mi < 2; mi++) {
                int base = wm * 32 + mi * 16;
                a[mi][0] = Ab[(base + g)     * 36 + kb + tig];
                a[mi][1] = Ab[(base + g + 8) * 36 + kb + tig];
                a[mi][2] = Ab[(base + g)     * 36 + kb + tig + 4];
                a[mi][3] = Ab[(base + g + 8) * 36 + kb + tig + 4];
                asr[mi][0] = Al[(base + g)     * 36 + kb + tig];
                asr[mi][1] = Al[(base + g + 8) * 36 + kb + tig];
                asr[mi][2] = Al[(base + g)     * 36 + kb + tig + 4];
                asr[mi][3] = Al[(base + g + 8) * 36 + kb + tig + 4];
            }
            float b[4][2], bs[4][2];
#pragma unroll
            for (int ni = 0; ni < 4; ni++) {
                int nb = wn * 32 + ni * 8;
                b[ni][0] = Bb[(nb + g) * 36 + kb + tig];
                b[ni][1] = Bb[(nb + g) * 36 + kb + tig + 4];
                bs[ni][0] = Bl[(nb + g) * 36 + kb + tig];
                bs[ni][1] = Bl[(nb + g) * 36 + kb + tig + 4];
            }
#pragma unroll
            for (int mi = 0; mi < 2; mi++)
#pragma unroll
                for (int ni = 0; ni < 4; ni++) {
                    mma_tf32(acc[mi][ni], a[mi], b[ni]);
                    mma_tf32(acc[mi][ni], a[mi], bs[ni]);
                    mma_tf32(acc[mi][ni], asr[mi], b[ni]);
                }
        }
    }

#pragma unroll
    for (int mi = 0; mi < 2; mi++)
#pragma unroll
        for (int ni = 0; ni < 4; ni++)
#pragma unroll
            for (int e = 0; e < 4; e++) {
                int m = m0 + wm * 32 + mi * 16 + g + ((e >> 1) * 8);
                int n = n0 + wn * 32 + ni * 8 + tig * 2 + (e & 1);
                dst[(size_t)m * EMBx + n] = acc[mi][ni][e] + bias[n];
            }
}

// ---------------------------------------------------------------------------
extern "C" void kernel_launch(void* const* d_in, const int* in_sizes, int n_in,
                              void* d_out, int out_size)
{
    (void)in_sizes; (void)n_in; (void)out_size;
    const float* x    = (const float*)d_in[0];
    const float* rel  = (const float*)d_in[1];
    const float* xlm  = (const float*)d_in[2];
    const float* knn  = (const float*)d_in[3];
    const float* Wq   = (const float*)d_in[4];
    const float* bq   = (const float*)d_in[5];
    const float* Wk   = (const float*)d_in[6];
    const float* bk   = (const float*)d_in[7];
    const float* Wv   = (const float*)d_in[8];
    const float* bv   = (const float*)d_in[9];
    const float* Wo   = (const float*)d_in[10];
    const float* bo   = (const float*)d_in[11];
    const float* gate = (const float*)d_in[12];

    float* out   = (float*)d_out;
    float* kvout = out + (size_t)Bx * Sx * EMBx;

    const int gsm = 2 * (128 * 36 + 64 * 36) * (int)sizeof(float);   // 55,296
    cudaFuncSetAttribute(qkv_gemm,
                         cudaFuncAttributeMaxDynamicSharedMemorySize, gsm);
    qkv_gemm<<<1792, 256, gsm>>>(x, Wq, bq, Wk, bk, Wv, bv, xlm, kvout);

    // Qs 128*68 + Ks 64*68 + Vs 64*68 + Pw 8*32*36 = 26,624 floats = 106,496 B
    const int asmem = (128 * 68 + 2 * 64 * 68 + 8 * 32 * 36) * (int)sizeof(float);
    cudaFuncSetAttribute(attn_knn,
                         cudaFuncAttributeMaxDynamicSharedMemorySize, asmem);
    attn_knn<<<4352, 256, asmem>>>(rel, gate, knn);

    cudaFuncSetAttribute(out_gemm,
                         cudaFuncAttributeMaxDynamicSharedMemorySize, gsm);
    out_gemm<<<dim3(32, 8), 256, gsm>>>(Wo, bo, out);
}

// round 10
// speedup vs baseline: 1.0542x; 1.0542x over previous
#include <cuda_runtime.h>
#include <cstdint>

#define Bx   4
#define Sx   1024
#define Hx   8
#define Dx   64
#define HDx  512
#define EMBx 512
#define XLx  1024
#define Jx   2048
#define KKx  32

// ---------------- device scratch ----------------
__device__ float g_q[Bx * Hx * Sx * Dx];     // exact (knn reads it)
__device__ float g_k[Bx * Hx * Jx * Dx];     // tf32-rounded at producer
__device__ float g_v[Bx * Hx * Jx * Dx];     // tf32-rounded at producer
__device__ float g_loc[Bx * Hx * Sx * Dx];   // g * local attn out
__device__ float g_ext[Bx * Sx * HDx];       // (1-g) * knn out

// ---------------- helpers ----------------
__device__ __forceinline__ float tf32r(float x) {
    uint32_t u;
    asm("cvt.rna.tf32.f32 %0, %1;" : "=r"(u) : "f"(x));
    return __uint_as_float(u);
}
__device__ __forceinline__ float4 tf32r4(float4 f) {
    f.x = tf32r(f.x); f.y = tf32r(f.y); f.z = tf32r(f.z); f.w = tf32r(f.w);
    return f;
}
__device__ __forceinline__ void mma_tf32(float* c, const float* a, const float* b)
{
    asm volatile(
        "mma.sync.aligned.m16n8k8.row.col.f32.tf32.tf32.f32 "
        "{%0,%1,%2,%3},{%4,%5,%6,%7},{%8,%9},{%0,%1,%2,%3};\n"
        : "+f"(c[0]), "+f"(c[1]), "+f"(c[2]), "+f"(c[3])
        : "r"(__float_as_uint(a[0])), "r"(__float_as_uint(a[1])),
          "r"(__float_as_uint(a[2])), "r"(__float_as_uint(a[3])),
          "r"(__float_as_uint(b[0])), "r"(__float_as_uint(b[1])));
}

// ===========================================================================
// Fused QKV projection GEMM (+ xl_memory copy blocks).  (round-7 version)
// ===========================================================================
__global__ __launch_bounds__(256) void qkv_gemm(
    const float* __restrict__ x,
    const float* __restrict__ Wq, const float* __restrict__ bq,
    const float* __restrict__ Wk, const float* __restrict__ bk,
    const float* __restrict__ Wv, const float* __restrict__ bv,
    const float* __restrict__ xlm,
    float* __restrict__ kvout)
{
    extern __shared__ float smg[];

    if (blockIdx.x >= 768) {
        int base = (blockIdx.x - 768) * 1024;
#pragma unroll
        for (int i = 0; i < 4; i++) {
            int idx = base + i * 256 + threadIdx.x;
            int n4 = idx & 127;
            int rest = idx >> 7;
            int c = rest & 1;  rest >>= 1;
            int j = rest & 1023;
            int b = rest >> 10;
            float4 f = tf32r4(((const float4*)xlm)[idx]);
            int n = n4 * 4;
            int h = n >> 6, d = n & 63;
            float* dst = (c ? g_v : g_k) + (((size_t)(b * Hx + h)) * Jx + j) * Dx + d;
            *(float4*)dst = f;
        }
        return;
    }

    float* Ab = smg;
    float* Bb = Ab + 128 * 36;
    float* Al = Bb + 64 * 36;
    float* Bl = Al + 128 * 36;

    int bm   = blockIdx.x & 31;
    int nbi  = blockIdx.x >> 5;
    int nsec = nbi >> 3;
    int m0 = bm * 128, n0 = (nbi & 7) * 64;
    bool s3 = (nsec != 0);

    const float* W    = (nsec == 0) ? Wq : (nsec == 1) ? Wk : Wv;
    const float* bias = (nsec == 0) ? bq : (nsec == 1) ? bk : bv;

    int tid = threadIdx.x;
    int wid = tid >> 5, lane = tid & 31;
    int wm = wid & 3, wn = wid >> 2;
    int g = lane >> 2, tig = lane & 3;

    float acc[2][4][4];
#pragma unroll
    for (int i = 0; i < 2; i++)
#pragma unroll
        for (int j = 0; j < 4; j++)
#pragma unroll
            for (int e = 0; e < 4; e++) acc[i][j][e] = 0.f;

    int a_row = tid >> 1;
    int a_c0  = (tid & 1) * 16;
    int b_row = tid >> 2;
    int b_c0  = (tid & 3) * 8;

    const float* Agp = x + (size_t)(m0 + a_row) * 512 + a_c0;
    const float* Wgp = W + (size_t)(n0 + b_row) * 512 + b_c0;

    for (int kc = 0; kc < 16; kc++) {
        int k0 = kc * 32;
        float4 ra[4], rb[2];
#pragma unroll
        for (int i = 0; i < 4; i++) ra[i] = *(const float4*)(Agp + k0 + i * 4);
#pragma unroll
        for (int i = 0; i < 2; i++) rb[i] = *(const float4*)(Wgp + k0 + i * 4);
        __syncthreads();
#pragma unroll
        for (int i = 0; i < 4; i++) {
            float4 f = ra[i];
            float4 bg = tf32r4(f);
            *(float4*)&Ab[a_row * 36 + a_c0 + i * 4] = bg;
            if (s3) {
                float4 sl;
                sl.x = tf32r(f.x - bg.x); sl.y = tf32r(f.y - bg.y);
                sl.z = tf32r(f.z - bg.z); sl.w = tf32r(f.w - bg.w);
                *(float4*)&Al[a_row * 36 + a_c0 + i * 4] = sl;
            }
        }
#pragma unroll
        for (int i = 0; i < 2; i++) {
            float4 f = rb[i];
            float4 bg = tf32r4(f);
            *(float4*)&Bb[b_row * 36 + b_c0 + i * 4] = bg;
            if (s3) {
                float4 sl;
                sl.x = tf32r(f.x - bg.x); sl.y = tf32r(f.y - bg.y);
                sl.z = tf32r(f.z - bg.z); sl.w = tf32r(f.w - bg.w);
                *(float4*)&Bl[b_row * 36 + b_c0 + i * 4] = sl;
            }
        }
        __syncthreads();

#pragma unroll
        for (int kk = 0; kk < 4; kk++) {
            int kb = kk * 8;
            float a[2][4], as[2][4];
#pragma unroll
            for (int mi = 0; mi < 2; mi++) {
                int base = wm * 32 + mi * 16;
                a[mi][0] = Ab[(base + g)     * 36 + kb + tig];
                a[mi][1] = Ab[(base + g + 8) * 36 + kb + tig];
                a[mi][2] = Ab[(base + g)     * 36 + kb + tig + 4];
                a[mi][3] = Ab[(base + g + 8) * 36 + kb + tig + 4];
                if (s3) {
                    as[mi][0] = Al[(base + g)     * 36 + kb + tig];
                    as[mi][1] = Al[(base + g + 8) * 36 + kb + tig];
                    as[mi][2] = Al[(base + g)     * 36 + kb + tig + 4];
                    as[mi][3] = Al[(base + g + 8) * 36 + kb + tig + 4];
                }
            }
            float b[4][2], bs[4][2];
#pragma unroll
            for (int ni = 0; ni < 4; ni++) {
                int nb = wn * 32 + ni * 8;
                b[ni][0] = Bb[(nb + g) * 36 + kb + tig];
                b[ni][1] = Bb[(nb + g) * 36 + kb + tig + 4];
                if (s3) {
                    bs[ni][0] = Bl[(nb + g) * 36 + kb + tig];
                    bs[ni][1] = Bl[(nb + g) * 36 + kb + tig + 4];
                }
            }
#pragma unroll
            for (int mi = 0; mi < 2; mi++)
#pragma unroll
                for (int ni = 0; ni < 4; ni++) {
                    mma_tf32(acc[mi][ni], a[mi], b[ni]);
                    if (s3) {
                        mma_tf32(acc[mi][ni], a[mi], bs[ni]);
                        mma_tf32(acc[mi][ni], as[mi], b[ni]);
                    }
                }
        }
    }

#pragma unroll
    for (int mi = 0; mi < 2; mi++) {
#pragma unroll
        for (int ni = 0; ni < 4; ni++) {
#pragma unroll
            for (int e = 0; e < 4; e++) {
                int m = m0 + wm * 32 + mi * 16 + g + ((e >> 1) * 8);
                int n = n0 + wn * 32 + ni * 8 + tig * 2 + (e & 1);
                float c = acc[mi][ni][e] + bias[n];
                int b = m >> 10, s = m & 1023;
                int h = n >> 6, d = n & 63;
                if (nsec == 0) {
                    g_q[(((size_t)(b * Hx + h)) * Sx + s) * Dx + d] = c;
                } else if (nsec == 1) {
                    g_k[(((size_t)(b * Hx + h)) * Jx + XLx + s) * Dx + d] = tf32r(c);
                    kvout[(((size_t)(b * Sx + s)) * 2 + 0) * HDx + n] = c;
                } else {
                    g_v[(((size_t)(b * Hx + h)) * Jx + XLx + s) * Dx + d] = tf32r(c);
                    kvout[(((size_t)(b * Sx + s)) * 2 + 1) * HDx + n] = c;
                }
            }
        }
    }
}

// ===========================================================================
// kNN attention (separate kernel, 64 KB smem -> 3 blocks/SM).
// One block per (b,s); 256 threads stream 2 x 64KB chunks coalesced.
// ===========================================================================
__global__ __launch_bounds__(256) void knn_kernel(const float* __restrict__ gate,
                                                  const float* __restrict__ knn)
{
    extern __shared__ float sm[];
    int tid = threadIdx.x;
    int wid = tid >> 5, lane = tid & 31;

    int b = blockIdx.x >> 10, s = blockIdx.x & 1023;
    int h = wid;

    const float* qp = g_q + (((size_t)(b * Hx + h)) * Sx + s) * Dx;
    float2 qv = *(const float2*)(qp + lane * 2);

    const float4* src =
        (const float4*)(knn + ((size_t)(b * Sx + s)) * (KKx * 2 * HDx));
    float4* dstv = (float4*)sm;              // 4096 float4 = 64KB

    float m = -1e30f, l = 0.f, a0 = 0.f, a1 = 0.f;

#pragma unroll
    for (int c = 0; c < 2; c++) {
        __syncthreads();
#pragma unroll
        for (int i = 0; i < 16; i++) {
            int idx = tid + i * 256;
            dstv[idx] = src[c * 4096 + idx];
        }
        __syncthreads();

        float sc[16];
#pragma unroll
        for (int kk = 0; kk < 16; kk++) {
            float2 kf = *(const float2*)(sm + kk * 1024 + h * 64 + lane * 2);
            float p = qv.x * kf.x + qv.y * kf.y;
            p += __shfl_xor_sync(0xffffffffu, p, 16);
            p += __shfl_xor_sync(0xffffffffu, p, 8);
            p += __shfl_xor_sync(0xffffffffu, p, 4);
            p += __shfl_xor_sync(0xffffffffu, p, 2);
            p += __shfl_xor_sync(0xffffffffu, p, 1);
            sc[kk] = p * 0.125f;
        }
        float cm = sc[0];
#pragma unroll
        for (int kk = 1; kk < 16; kk++) cm = fmaxf(cm, sc[kk]);
        float mn = fmaxf(m, cm);
        float al = __expf(m - mn);
        a0 *= al; a1 *= al; l *= al;
#pragma unroll
        for (int kk = 0; kk < 16; kk++) {
            float p = __expf(sc[kk] - mn);
            l += p;
            float2 vf = *(const float2*)(sm + kk * 1024 + 512 + h * 64 + lane * 2);
            a0 = fmaf(p, vf.x, a0);
            a1 = fmaf(p, vf.y, a1);
        }
        m = mn;
    }

    float gg = 1.f / (1.f + __expf(-gate[h]));
    float w = (1.f - gg) / l;
    float2 st; st.x = w * a0; st.y = w * a1;
    *(float2*)&g_ext[((size_t)(b * Sx + s)) * HDx + h * 64 + lane * 2] = st;
}

// ===========================================================================
// Local causal XL attention (separate kernel, round-7 body).
// 512 blocks; long blocks (high qt) scheduled first; mask only last key-tile.
// ===========================================================================
__global__ __launch_bounds__(256) void attn_kernel(const float* __restrict__ rel,
                                                   const float* __restrict__ gate)
{
    extern __shared__ float sm[];
    int tid = threadIdx.x;
    int wid = tid >> 5, lane = tid & 31;

    float* Qs = sm;                       // [64][68]
    float* Ks = Qs + 64 * 68;             // [64][68]
    float* Vs = Ks + 64 * 68;             // [64][68]
    float* Pw = Vs + 64 * 68 + wid * 576; // per-warp [16][36]

    int bh = blockIdx.x >> 4;             // 0..31
    int h = bh & 7;
    int qt = 15 - (blockIdx.x & 15);      // long blocks first
    int i0 = qt * 64;
    int wm = wid & 3, wn = wid >> 2;
    int g = lane >> 2, tig = lane & 3;
    int r0 = wm * 16 + g, r1 = r0 + 8;
    int qi0 = i0 + r0, qi1 = i0 + r1;

    const float* qbase = g_q + (((size_t)bh) * Sx + i0) * Dx;
    for (int idx = tid; idx < 1024; idx += 256) {
        int row = idx >> 4, c4 = idx & 15;
        *(float4*)&Qs[row * 68 + c4 * 4] =
            tf32r4(*(const float4*)(qbase + row * 64 + c4 * 4));
    }

    float o[8][4];
#pragma unroll
    for (int ni = 0; ni < 8; ni++)
#pragma unroll
        for (int e = 0; e < 4; e++) o[ni][e] = 0.f;
    float m0 = -1e30f, m1 = -1e30f, l0 = 0.f, l1 = 0.f;

    int ntiles = qt + 17;
    const float* kbase = g_k + ((size_t)bh) * Jx * Dx;
    const float* vbase = g_v + ((size_t)bh) * Jx * Dx;
    const float* relrow0 = rel + ((size_t)h * Sx + qi0) * Jx;
    const float* relrow1 = rel + ((size_t)h * Sx + qi1) * Jx;

    for (int t = 0; t < ntiles; t++) {
        int j0 = t * 64;
        __syncthreads();
        for (int idx = tid; idx < 1024; idx += 256) {
            int row = idx >> 4, c4 = idx & 15;
            *(float4*)&Ks[row * 68 + c4 * 4] =
                *(const float4*)(kbase + (size_t)(j0 + row) * 64 + c4 * 4);
            *(float4*)&Vs[row * 68 + c4 * 4] =
                *(const float4*)(vbase + (size_t)(j0 + row) * 64 + c4 * 4);
        }
        __syncthreads();

        float c[4][4];
#pragma unroll
        for (int ni = 0; ni < 4; ni++)
#pragma unroll
            for (int e = 0; e < 4; e++) c[ni][e] = 0.f;
#pragma unroll
        for (int kk = 0; kk < 8; kk++) {
            int kb = kk * 8;
            float a[4];
            a[0] = Qs[r0 * 68 + kb + tig];
            a[1] = Qs[r1 * 68 + kb + tig];
            a[2] = Qs[r0 * 68 + kb + tig + 4];
            a[3] = Qs[r1 * 68 + kb + tig + 4];
#pragma unroll
            for (int ni = 0; ni < 4; ni++) {
                int krow = wn * 32 + ni * 8 + g;
                float b[2];
                b[0] = Ks[krow * 68 + kb + tig];
                b[1] = Ks[krow * 68 + kb + tig + 4];
                mma_tf32(c[ni], a, b);
            }
        }

        // rel_pos + scale; causal mask only possible on the last tile
        if (t == ntiles - 1) {
#pragma unroll
            for (int ni = 0; ni < 4; ni++) {
                int kcol = wn * 32 + ni * 8 + tig * 2;
                int kj = j0 + kcol;
                float2 rp0 = *(const float2*)(relrow0 + kj);
                float2 rp1 = *(const float2*)(relrow1 + kj);
                c[ni][0] = (kj     <= qi0 + XLx) ? (c[ni][0] + rp0.x) * 0.125f : -1e30f;
                c[ni][1] = (kj + 1 <= qi0 + XLx) ? (c[ni][1] + rp0.y) * 0.125f : -1e30f;
                c[ni][2] = (kj     <= qi1 + XLx) ? (c[ni][2] + rp1.x) * 0.125f : -1e30f;
                c[ni][3] = (kj + 1 <= qi1 + XLx) ? (c[ni][3] + rp1.y) * 0.125f : -1e30f;
            }
        } else {
#pragma unroll
            for (int ni = 0; ni < 4; ni++) {
                int kcol = wn * 32 + ni * 8 + tig * 2;
                int kj = j0 + kcol;
                float2 rp0 = *(const float2*)(relrow0 + kj);
                float2 rp1 = *(const float2*)(relrow1 + kj);
                c[ni][0] = (c[ni][0] + rp0.x) * 0.125f;
                c[ni][1] = (c[ni][1] + rp0.y) * 0.125f;
                c[ni][2] = (c[ni][2] + rp1.x) * 0.125f;
                c[ni][3] = (c[ni][3] + rp1.y) * 0.125f;
            }
        }

        float rm0 = -1e30f, rm1 = -1e30f;
#pragma unroll
        for (int ni = 0; ni < 4; ni++) {
            rm0 = fmaxf(rm0, fmaxf(c[ni][0], c[ni][1]));
            rm1 = fmaxf(rm1, fmaxf(c[ni][2], c[ni][3]));
        }
        rm0 = fmaxf(rm0, __shfl_xor_sync(0xffffffffu, rm0, 1));
        rm0 = fmaxf(rm0, __shfl_xor_sync(0xffffffffu, rm0, 2));
        rm1 = fmaxf(rm1, __shfl_xor_sync(0xffffffffu, rm1, 1));
        rm1 = fmaxf(rm1, __shfl_xor_sync(0xffffffffu, rm1, 2));
        float mn0 = fmaxf(m0, rm0), mn1 = fmaxf(m1, rm1);
        float al0 = __expf(m0 - mn0), al1 = __expf(m1 - mn1);
        float ls0 = 0.f, ls1 = 0.f;
#pragma unroll
        for (int ni = 0; ni < 4; ni++) {
            int kcol = ni * 8 + tig * 2;
            float p00 = tf32r(__expf(c[ni][0] - mn0));
            float p01 = tf32r(__expf(c[ni][1] - mn0));
            float p10 = tf32r(__expf(c[ni][2] - mn1));
            float p11 = tf32r(__expf(c[ni][3] - mn1));
            ls0 += p00 + p01; ls1 += p10 + p11;
            Pw[g * 36 + kcol]           = p00;
            Pw[g * 36 + kcol + 1]       = p01;
            Pw[(g + 8) * 36 + kcol]     = p10;
            Pw[(g + 8) * 36 + kcol + 1] = p11;
        }
        ls0 += __shfl_xor_sync(0xffffffffu, ls0, 1);
        ls0 += __shfl_xor_sync(0xffffffffu, ls0, 2);
        ls1 += __shfl_xor_sync(0xffffffffu, ls1, 1);
        ls1 += __shfl_xor_sync(0xffffffffu, ls1, 2);
        l0 = l0 * al0 + ls0;
        l1 = l1 * al1 + ls1;
        m0 = mn0; m1 = mn1;
#pragma unroll
        for (int ni = 0; ni < 8; ni++) {
            o[ni][0] *= al0; o[ni][1] *= al0;
            o[ni][2] *= al1; o[ni][3] *= al1;
        }
        __syncwarp();

#pragma unroll
        for (int kk = 0; kk < 4; kk++) {
            int kb = kk * 8;
            float a[4];
            a[0] = Pw[g * 36 + kb + tig];
            a[1] = Pw[(g + 8) * 36 + kb + tig];
            a[2] = Pw[g * 36 + kb + tig + 4];
            a[3] = Pw[(g + 8) * 36 + kb + tig + 4];
            int vrow = wn * 32 + kb + tig;
#pragma unroll
            for (int ni = 0; ni < 8; ni++) {
                float b[2];
                b[0] = Vs[vrow * 68 + ni * 8 + g];
                b[1] = Vs[(vrow + 4) * 68 + ni * 8 + g];
                mma_tf32(o[ni], a, b);
            }
        }
    }

    __syncthreads();
    if (wn == 1) {
        float* M = Ks + (wm * 16) * 68;
#pragma unroll
        for (int ni = 0; ni < 8; ni++) {
            int col = ni * 8 + tig * 2;
            M[g * 68 + col]           = o[ni][0];
            M[g * 68 + col + 1]       = o[ni][1];
            M[(g + 8) * 68 + col]     = o[ni][2];
            M[(g + 8) * 68 + col + 1] = o[ni][3];
        }
        if (tig == 0) {
            Vs[r0] = m0; Vs[r1] = m1;
            Vs[64 + r0] = l0; Vs[64 + r1] = l1;
        }
    }
    __syncthreads();
    if (wn == 0) {
        float gsig = 1.f / (1.f + __expf(-gate[h]));
        float m1p0 = Vs[r0], m1p1 = Vs[r1];
        float l1p0 = Vs[64 + r0], l1p1 = Vs[64 + r1];
        float mt0 = fmaxf(m0, m1p0), mt1 = fmaxf(m1, m1p1);
        float a00 = __expf(m0 - mt0),   a01 = __expf(m1p0 - mt0);
        float a10 = __expf(m1 - mt1),   a11 = __expf(m1p1 - mt1);
        float inv0 = gsig / (l0 * a00 + l1p0 * a01);
        float inv1 = gsig / (l1 * a10 + l1p1 * a11);
        float* M = Ks + (wm * 16) * 68;
#pragma unroll
        for (int ni = 0; ni < 8; ni++) {
            int col = ni * 8 + tig * 2;
            float2 s0, s1;
            s0.x = (o[ni][0] * a00 + M[g * 68 + col]           * a01) * inv0;
            s0.y = (o[ni][1] * a00 + M[g * 68 + col + 1]       * a01) * inv0;
            s1.x = (o[ni][2] * a10 + M[(g + 8) * 68 + col]     * a11) * inv1;
            s1.y = (o[ni][3] * a10 + M[(g + 8) * 68 + col + 1] * a11) * inv1;
            *(float2*)&g_loc[(((size_t)bh) * Sx + qi0) * Dx + col] = s0;
            *(float2*)&g_loc[(((size_t)bh) * Sx + qi1) * Dx + col] = s1;
        }
    }
}

// ===========================================================================
// Output projection: out[4096,512] = (g_loc + g_ext) @ Wo^T + bo (3xTF32)
// ===========================================================================
__global__ __launch_bounds__(256) void out_gemm(const float* __restrict__ W,
                                                const float* __restrict__ bias,
                                                float* __restrict__ dst)
{
    extern __shared__ float smg[];
    float* Ab = smg;
    float* Bb = Ab + 128 * 36;
    float* Al = Bb + 64 * 36;
    float* Bl = Al + 128 * 36;

    int tid = threadIdx.x;
    int wid = tid >> 5, lane = tid & 31;
    int wm = wid & 3, wn = wid >> 2;
    int g = lane >> 2, tig = lane & 3;
    int m0 = blockIdx.x * 128, n0 = blockIdx.y * 64;

    float acc[2][4][4];
#pragma unroll
    for (int i = 0; i < 2; i++)
#pragma unroll
        for (int j = 0; j < 4; j++)
#pragma unroll
            for (int e = 0; e < 4; e++) acc[i][j][e] = 0.f;

    int a_row = tid >> 1;
    int a_c0  = (tid & 1) * 16;
    int b_row = tid >> 2;
    int b_c0  = (tid & 3) * 8;

    int mrow = m0 + a_row;
    int ab = mrow >> 10, as_ = mrow & 1023;
    const float* extp = g_ext + (size_t)mrow * 512;
    const float* Wgp = W + (size_t)(n0 + b_row) * 512 + b_c0;

    for (int kc = 0; kc < 16; kc++) {
        int k0 = kc * 32;
        float4 ra[4], rb[2];
#pragma unroll
        for (int i = 0; i < 4; i++) {
            int cc = a_c0 + k0 + i * 4;
            int hh = cc >> 6, dd = cc & 63;
            float4 f1 = *(const float4*)&g_loc[(((size_t)(ab * Hx + hh)) * Sx + as_) * Dx + dd];
            float4 f2 = *(const float4*)(extp + cc);
            ra[i].x = f1.x + f2.x; ra[i].y = f1.y + f2.y;
            ra[i].z = f1.z + f2.z; ra[i].w = f1.w + f2.w;
        }
#pragma unroll
        for (int i = 0; i < 2; i++) rb[i] = *(const float4*)(Wgp + k0 + i * 4);
        __syncthreads();
#pragma unroll
        for (int i = 0; i < 4; i++) {
            float4 f = ra[i];
            float4 bg = tf32r4(f);
            *(float4*)&Ab[a_row * 36 + a_c0 + i * 4] = bg;
            float4 sl;
            sl.x = tf32r(f.x - bg.x); sl.y = tf32r(f.y - bg.y);
            sl.z = tf32r(f.z - bg.z); sl.w = tf32r(f.w - bg.w);
            *(float4*)&Al[a_row * 36 + a_c0 + i * 4] = sl;
        }
#pragma unroll
        for (int i = 0; i < 2; i++) {
            float4 f = rb[i];
            float4 bg = tf32r4(f);
            *(float4*)&Bb[b_row * 36 + b_c0 + i * 4] = bg;
            float4 sl;
            sl.x = tf32r(f.x - bg.x); sl.y = tf32r(f.y - bg.y);
            sl.z = tf32r(f.z - bg.z); sl.w = tf32r(f.w - bg.w);
            *(float4*)&Bl[b_row * 36 + b_c0 + i * 4] = sl;
        }
        __syncthreads();

#pragma unroll
        for (int kk = 0; kk < 4; kk++) {
            int kb = kk * 8;
            float a[2][4], asr[2][4];
#pragma unroll
            for (int mi = 0; mi < 2; mi++) {
                int base = wm * 32 + mi * 16;
                a[mi][0] = Ab[(base + g)     * 36 + kb + tig];
                a[mi][1] = Ab[(base + g + 8) * 36 + kb + tig];
                a[mi][2] = Ab[(base + g)     * 36 + kb + tig + 4];
                a[mi][3] = Ab[(base + g + 8) * 36 + kb + tig + 4];
                asr[mi][0] = Al[(base + g)     * 36 + kb + tig];
                asr[mi][1] = Al[(base + g + 8) * 36 + kb + tig];
                asr[mi][2] = Al[(base + g)     * 36 + kb + tig + 4];
                asr[mi][3] = Al[(base + g + 8) * 36 + kb + tig + 4];
            }
            float b[4][2], bs[4][2];
#pragma unroll
            for (int ni = 0; ni < 4; ni++) {
                int nb = wn * 32 + ni * 8;
                b[ni][0] = Bb[(nb + g) * 36 + kb + tig];
                b[ni][1] = Bb[(nb + g) * 36 + kb + tig + 4];
                bs[ni][0] = Bl[(nb + g) * 36 + kb + tig];
                bs[ni][1] = Bl[(nb + g) * 36 + kb + tig + 4];
            }
#pragma unroll
            for (int mi = 0; mi < 2; mi++)
#pragma unroll
                for (int ni = 0; ni < 4; ni++) {
                    mma_tf32(acc[mi][ni], a[mi], b[ni]);
                    mma_tf32(acc[mi][ni], a[mi], bs[ni]);
                    mma_tf32(acc[mi][ni], asr[mi], b[ni]);
                }
        }
    }

#pragma unroll
    for (int mi = 0; mi < 2; mi++)
#pragma unroll
        for (int ni = 0; ni < 4; ni++)
#pragma unroll
            for (int e = 0; e < 4; e++) {
                int m = m0 + wm * 32 + mi * 16 + g + ((e >> 1) * 8);
                int n = n0 + wn * 32 + ni * 8 + tig * 2 + (e & 1);
                dst[(size_t)m * EMBx + n] = acc[mi][ni][e] + bias[n];
            }
}

// ---------------------------------------------------------------------------
extern "C" void kernel_launch(void* const* d_in, const int* in_sizes, int n_in,
                              void* d_out, int out_size)
{
    (void)in_sizes; (void)n_in; (void)out_size;
    const float* x    = (const float*)d_in[0];
    const float* rel  = (const float*)d_in[1];
    const float* xlm  = (const float*)d_in[2];
    const float* knn  = (const float*)d_in[3];
    const float* Wq   = (const float*)d_in[4];
    const float* bq   = (const float*)d_in[5];
    const float* Wk   = (const float*)d_in[6];
    const float* bk   = (const float*)d_in[7];
    const float* Wv   = (const float*)d_in[8];
    const float* bv   = (const float*)d_in[9];
    const float* Wo   = (const float*)d_in[10];
    const float* bo   = (const float*)d_in[11];
    const float* gate = (const float*)d_in[12];

    float* out   = (float*)d_out;
    float* kvout = out + (size_t)Bx * Sx * EMBx;

    const int gsm = 2 * (128 * 36 + 64 * 36) * (int)sizeof(float);   // 55,296
    cudaFuncSetAttribute(qkv_gemm,
                         cudaFuncAttributeMaxDynamicSharedMemorySize, gsm);
    qkv_gemm<<<1792, 256, gsm>>>(x, Wq, bq, Wk, bk, Wv, bv, xlm, kvout);

    const int ksm = 64 * 1024;                                        // 65,536
    cudaFuncSetAttribute(knn_kernel,
                         cudaFuncAttributeMaxDynamicSharedMemorySize, ksm);
    knn_kernel<<<4096, 256, ksm>>>(gate, knn);

    const int asmem = (3 * 64 * 68 + 8 * 576) * (int)sizeof(float);   // 70,656
    cudaFuncSetAttribute(attn_kernel,
                         cudaFuncAttributeMaxDynamicSharedMemorySize, asmem);
    attn_kernel<<<512, 256, asmem>>>(rel, gate);

    cudaFuncSetAttribute(out_gemm,
                         cudaFuncAttributeMaxDynamicSharedMemorySize, gsm);
    out_gemm<<<dim3(32, 8), 256, gsm>>>(Wo, bo, out);
}

// round 11
// speedup vs baseline: 1.1885x; 1.1274x over previous
#include <cuda_runtime.h>
#include <cuda_fp16.h>
#include <cstdint>

#define Bx   4
#define Sx   1024
#define Hx   8
#define Dx   64
#define HDx  512
#define EMBx 512
#define XLx  1024
#define Jx   2048
#define KKx  32

#define RSCL 2048.0f
#define RINV 4.8828125e-4f   // 1/2048

// ---------------- device scratch ----------------
__device__ float g_q[Bx * Hx * Sx * Dx];     // exact (knn reads it)
__device__ float g_k[Bx * Hx * Jx * Dx];     // tf32-rounded at producer
__device__ float g_v[Bx * Hx * Jx * Dx];     // tf32-rounded at producer
__device__ float g_loc[Bx * Hx * Sx * Dx];   // g * local attn out
__device__ float g_ext[Bx * Sx * HDx];       // (1-g) * knn out

// ---------------- helpers ----------------
__device__ __forceinline__ float tf32r(float x) {
    uint32_t u;
    asm("cvt.rna.tf32.f32 %0, %1;" : "=r"(u) : "f"(x));
    return __uint_as_float(u);
}
__device__ __forceinline__ float4 tf32r4(float4 f) {
    f.x = tf32r(f.x); f.y = tf32r(f.y); f.z = tf32r(f.z); f.w = tf32r(f.w);
    return f;
}
__device__ __forceinline__ void mma_tf32(float* c, const float* a, const float* b)
{
    asm volatile(
        "mma.sync.aligned.m16n8k8.row.col.f32.tf32.tf32.f32 "
        "{%0,%1,%2,%3},{%4,%5,%6,%7},{%8,%9},{%0,%1,%2,%3};\n"
        : "+f"(c[0]), "+f"(c[1]), "+f"(c[2]), "+f"(c[3])
        : "r"(__float_as_uint(a[0])), "r"(__float_as_uint(a[1])),
          "r"(__float_as_uint(a[2])), "r"(__float_as_uint(a[3])),
          "r"(__float_as_uint(b[0])), "r"(__float_as_uint(b[1])));
}
__device__ __forceinline__ void mma_f16(float* c, const uint32_t* a, const uint32_t* b)
{
    asm volatile(
        "mma.sync.aligned.m16n8k16.row.col.f32.f16.f16.f32 "
        "{%0,%1,%2,%3},{%4,%5,%6,%7},{%8,%9},{%0,%1,%2,%3};\n"
        : "+f"(c[0]), "+f"(c[1]), "+f"(c[2]), "+f"(c[3])
        : "r"(a[0]), "r"(a[1]), "r"(a[2]), "r"(a[3]),
          "r"(b[0]), "r"(b[1]));
}
// split (x,y) into packed fp16 hi pair and 2048x-scaled residual pair
__device__ __forceinline__ void split2(float x, float y, uint32_t& hi, uint32_t& lo)
{
    __half hx = __float2half_rn(x), hy = __float2half_rn(y);
    float rx = (x - __half2float(hx)) * RSCL;
    float ry = (y - __half2float(hy)) * RSCL;
    __half2 h2 = __halves2half2(hx, hy);
    __half2 l2 = __halves2half2(__float2half_rn(rx), __float2half_rn(ry));
    hi = *(uint32_t*)&h2;
    lo = *(uint32_t*)&l2;
}

// ===========================================================================
// Fused QKV projection GEMM (+ xl_memory copy blocks).
// nsec 0 (Q): 1xTF32 path.  nsec 1/2 (K/V): 3xFP16 scaled-residual split.
// ===========================================================================
__global__ __launch_bounds__(256) void qkv_gemm(
    const float* __restrict__ x,
    const float* __restrict__ Wq, const float* __restrict__ bq,
    const float* __restrict__ Wk, const float* __restrict__ bk,
    const float* __restrict__ Wv, const float* __restrict__ bv,
    const float* __restrict__ xlm,
    float* __restrict__ kvout)
{
    extern __shared__ float smg[];

    if (blockIdx.x >= 768) {
        int base = (blockIdx.x - 768) * 1024;
#pragma unroll
        for (int i = 0; i < 4; i++) {
            int idx = base + i * 256 + threadIdx.x;
            int n4 = idx & 127;
            int rest = idx >> 7;
            int c = rest & 1;  rest >>= 1;
            int j = rest & 1023;
            int b = rest >> 10;
            float4 f = tf32r4(((const float4*)xlm)[idx]);
            int n = n4 * 4;
            int h = n >> 6, d = n & 63;
            float* dst = (c ? g_v : g_k) + (((size_t)(b * Hx + h)) * Jx + j) * Dx + d;
            *(float4*)dst = f;
        }
        return;
    }

    int bm   = blockIdx.x & 31;
    int nbi  = blockIdx.x >> 5;
    int nsec = nbi >> 3;
    int m0 = bm * 128, n0 = (nbi & 7) * 64;

    const float* W    = (nsec == 0) ? Wq : (nsec == 1) ? Wk : Wv;
    const float* bias = (nsec == 0) ? bq : (nsec == 1) ? bk : bv;

    int tid = threadIdx.x;
    int wid = tid >> 5, lane = tid & 31;
    int wm = wid & 3, wn = wid >> 2;
    int g = lane >> 2, tig = lane & 3;

    int a_row = tid >> 1;
    int a_c0  = (tid & 1) * 16;
    int b_row = tid >> 2;
    int b_c0  = (tid & 3) * 8;

    const float* Agp = x + (size_t)(m0 + a_row) * 512 + a_c0;
    const float* Wgp = W + (size_t)(n0 + b_row) * 512 + b_c0;

    if (nsec == 0) {
        // ---------------- Q: 1xTF32 path ----------------
        float* Ab = smg;                     // [128][36]
        float* Bb = Ab + 128 * 36;           // [64][36]

        float acc[2][4][4];
#pragma unroll
        for (int i = 0; i < 2; i++)
#pragma unroll
            for (int j = 0; j < 4; j++)
#pragma unroll
                for (int e = 0; e < 4; e++) acc[i][j][e] = 0.f;

        for (int kc = 0; kc < 16; kc++) {
            int k0 = kc * 32;
            float4 ra[4], rb[2];
#pragma unroll
            for (int i = 0; i < 4; i++) ra[i] = *(const float4*)(Agp + k0 + i * 4);
#pragma unroll
            for (int i = 0; i < 2; i++) rb[i] = *(const float4*)(Wgp + k0 + i * 4);
            __syncthreads();
#pragma unroll
            for (int i = 0; i < 4; i++)
                *(float4*)&Ab[a_row * 36 + a_c0 + i * 4] = tf32r4(ra[i]);
#pragma unroll
            for (int i = 0; i < 2; i++)
                *(float4*)&Bb[b_row * 36 + b_c0 + i * 4] = tf32r4(rb[i]);
            __syncthreads();

#pragma unroll
            for (int kk = 0; kk < 4; kk++) {
                int kb = kk * 8;
                float a[2][4];
#pragma unroll
                for (int mi = 0; mi < 2; mi++) {
                    int base = wm * 32 + mi * 16;
                    a[mi][0] = Ab[(base + g)     * 36 + kb + tig];
                    a[mi][1] = Ab[(base + g + 8) * 36 + kb + tig];
                    a[mi][2] = Ab[(base + g)     * 36 + kb + tig + 4];
                    a[mi][3] = Ab[(base + g + 8) * 36 + kb + tig + 4];
                }
                float b[4][2];
#pragma unroll
                for (int ni = 0; ni < 4; ni++) {
                    int nb = wn * 32 + ni * 8;
                    b[ni][0] = Bb[(nb + g) * 36 + kb + tig];
                    b[ni][1] = Bb[(nb + g) * 36 + kb + tig + 4];
                }
#pragma unroll
                for (int mi = 0; mi < 2; mi++)
#pragma unroll
                    for (int ni = 0; ni < 4; ni++)
                        mma_tf32(acc[mi][ni], a[mi], b[ni]);
            }
        }

#pragma unroll
        for (int mi = 0; mi < 2; mi++)
#pragma unroll
            for (int ni = 0; ni < 4; ni++)
#pragma unroll
                for (int e = 0; e < 4; e++) {
                    int m = m0 + wm * 32 + mi * 16 + g + ((e >> 1) * 8);
                    int n = n0 + wn * 32 + ni * 8 + tig * 2 + (e & 1);
                    float c = acc[mi][ni][e] + bias[n];
                    int b = m >> 10, s = m & 1023;
                    int h = n >> 6, d = n & 63;
                    g_q[(((size_t)(b * Hx + h)) * Sx + s) * Dx + d] = c;
                }
        return;
    }

    // ---------------- K/V: 3xFP16 scaled-residual path ----------------
    uint32_t* Ah = (uint32_t*)smg;          // [128][20] words (half2)
    uint32_t* Al = Ah + 128 * 20;
    uint32_t* Bh = Al + 128 * 20;
    uint32_t* Bl = Bh + 64 * 20;            // total 7680 words = 30,720 B

    float accM[2][4][4], accC[2][4][4];
#pragma unroll
    for (int i = 0; i < 2; i++)
#pragma unroll
        for (int j = 0; j < 4; j++)
#pragma unroll
            for (int e = 0; e < 4; e++) { accM[i][j][e] = 0.f; accC[i][j][e] = 0.f; }

    int aw0 = a_row * 20 + (a_c0 >> 1);
    int bw0 = b_row * 20 + (b_c0 >> 1);

    for (int kc = 0; kc < 16; kc++) {
        int k0 = kc * 32;
        float4 ra[4], rb[2];
#pragma unroll
        for (int i = 0; i < 4; i++) ra[i] = *(const float4*)(Agp + k0 + i * 4);
#pragma unroll
        for (int i = 0; i < 2; i++) rb[i] = *(const float4*)(Wgp + k0 + i * 4);
        __syncthreads();
#pragma unroll
        for (int i = 0; i < 4; i++) {
            uint32_t h0, l0, h1, l1;
            split2(ra[i].x, ra[i].y, h0, l0);
            split2(ra[i].z, ra[i].w, h1, l1);
            Ah[aw0 + i * 2]     = h0;  Ah[aw0 + i * 2 + 1] = h1;
            Al[aw0 + i * 2]     = l0;  Al[aw0 + i * 2 + 1] = l1;
        }
#pragma unroll
        for (int i = 0; i < 2; i++) {
            uint32_t h0, l0, h1, l1;
            split2(rb[i].x, rb[i].y, h0, l0);
            split2(rb[i].z, rb[i].w, h1, l1);
            Bh[bw0 + i * 2]     = h0;  Bh[bw0 + i * 2 + 1] = h1;
            Bl[bw0 + i * 2]     = l0;  Bl[bw0 + i * 2 + 1] = l1;
        }
        __syncthreads();

#pragma unroll
        for (int ks = 0; ks < 2; ks++) {
            int kw = ks * 8;
            uint32_t ah[2][4], al[2][4];
#pragma unroll
            for (int mi = 0; mi < 2; mi++) {
                int base = wm * 32 + mi * 16;
                int r0w = (base + g) * 20 + kw, r1w = (base + g + 8) * 20 + kw;
                ah[mi][0] = Ah[r0w + tig];     ah[mi][1] = Ah[r1w + tig];
                ah[mi][2] = Ah[r0w + tig + 4]; ah[mi][3] = Ah[r1w + tig + 4];
                al[mi][0] = Al[r0w + tig];     al[mi][1] = Al[r1w + tig];
                al[mi][2] = Al[r0w + tig + 4]; al[mi][3] = Al[r1w + tig + 4];
            }
            uint32_t bh[4][2], bl[4][2];
#pragma unroll
            for (int ni = 0; ni < 4; ni++) {
                int nw = (wn * 32 + ni * 8 + g) * 20 + kw;
                bh[ni][0] = Bh[nw + tig]; bh[ni][1] = Bh[nw + tig + 4];
                bl[ni][0] = Bl[nw + tig]; bl[ni][1] = Bl[nw + tig + 4];
            }
#pragma unroll
            for (int mi = 0; mi < 2; mi++)
#pragma unroll
                for (int ni = 0; ni < 4; ni++) {
                    mma_f16(accM[mi][ni], ah[mi], bh[ni]);
                    mma_f16(accC[mi][ni], ah[mi], bl[ni]);
                    mma_f16(accC[mi][ni], al[mi], bh[ni]);
                }
        }
    }

#pragma unroll
    for (int mi = 0; mi < 2; mi++)
#pragma unroll
        for (int ni = 0; ni < 4; ni++)
#pragma unroll
            for (int e = 0; e < 4; e++) {
                int m = m0 + wm * 32 + mi * 16 + g + ((e >> 1) * 8);
                int n = n0 + wn * 32 + ni * 8 + tig * 2 + (e & 1);
                float c = accM[mi][ni][e] + accC[mi][ni][e] * RINV + bias[n];
                int b = m >> 10, s = m & 1023;
                int h = n >> 6, d = n & 63;
                if (nsec == 1) {
                    g_k[(((size_t)(b * Hx + h)) * Jx + XLx + s) * Dx + d] = tf32r(c);
                    kvout[(((size_t)(b * Sx + s)) * 2 + 0) * HDx + n] = c;
                } else {
                    g_v[(((size_t)(b * Hx + h)) * Jx + XLx + s) * Dx + d] = tf32r(c);
                    kvout[(((size_t)(b * Sx + s)) * 2 + 1) * HDx + n] = c;
                }
            }
}

// ===========================================================================
// kNN attention (64 KB smem -> 3 blocks/SM). Unchanged from round 10.
// ===========================================================================
__global__ __launch_bounds__(256) void knn_kernel(const float* __restrict__ gate,
                                                  const float* __restrict__ knn)
{
    extern __shared__ float sm[];
    int tid = threadIdx.x;
    int wid = tid >> 5, lane = tid & 31;

    int b = blockIdx.x >> 10, s = blockIdx.x & 1023;
    int h = wid;

    const float* qp = g_q + (((size_t)(b * Hx + h)) * Sx + s) * Dx;
    float2 qv = *(const float2*)(qp + lane * 2);

    const float4* src =
        (const float4*)(knn + ((size_t)(b * Sx + s)) * (KKx * 2 * HDx));
    float4* dstv = (float4*)sm;

    float m = -1e30f, l = 0.f, a0 = 0.f, a1 = 0.f;

#pragma unroll
    for (int c = 0; c < 2; c++) {
        __syncthreads();
#pragma unroll
        for (int i = 0; i < 16; i++) {
            int idx = tid + i * 256;
            dstv[idx] = src[c * 4096 + idx];
        }
        __syncthreads();

        float sc[16];
#pragma unroll
        for (int kk = 0; kk < 16; kk++) {
            float2 kf = *(const float2*)(sm + kk * 1024 + h * 64 + lane * 2);
            float p = qv.x * kf.x + qv.y * kf.y;
            p += __shfl_xor_sync(0xffffffffu, p, 16);
            p += __shfl_xor_sync(0xffffffffu, p, 8);
            p += __shfl_xor_sync(0xffffffffu, p, 4);
            p += __shfl_xor_sync(0xffffffffu, p, 2);
            p += __shfl_xor_sync(0xffffffffu, p, 1);
            sc[kk] = p * 0.125f;
        }
        float cm = sc[0];
#pragma unroll
        for (int kk = 1; kk < 16; kk++) cm = fmaxf(cm, sc[kk]);
        float mn = fmaxf(m, cm);
        float al = __expf(m - mn);
        a0 *= al; a1 *= al; l *= al;
#pragma unroll
        for (int kk = 0; kk < 16; kk++) {
            float p = __expf(sc[kk] - mn);
            l += p;
            float2 vf = *(const float2*)(sm + kk * 1024 + 512 + h * 64 + lane * 2);
            a0 = fmaf(p, vf.x, a0);
            a1 = fmaf(p, vf.y, a1);
        }
        m = mn;
    }

    float gg = 1.f / (1.f + __expf(-gate[h]));
    float w = (1.f - gg) / l;
    float2 st; st.x = w * a0; st.y = w * a1;
    *(float2*)&g_ext[((size_t)(b * Sx + s)) * HDx + h * 64 + lane * 2] = st;
}

// ===========================================================================
// Local causal XL attention. Unchanged from round 10.
// ===========================================================================
__global__ __launch_bounds__(256) void attn_kernel(const float* __restrict__ rel,
                                                   const float* __restrict__ gate)
{
    extern __shared__ float sm[];
    int tid = threadIdx.x;
    int wid = tid >> 5, lane = tid & 31;

    float* Qs = sm;
    float* Ks = Qs + 64 * 68;
    float* Vs = Ks + 64 * 68;
    float* Pw = Vs + 64 * 68 + wid * 576;

    int bh = blockIdx.x >> 4;
    int h = bh & 7;
    int qt = 15 - (blockIdx.x & 15);
    int i0 = qt * 64;
    int wm = wid & 3, wn = wid >> 2;
    int g = lane >> 2, tig = lane & 3;
    int r0 = wm * 16 + g, r1 = r0 + 8;
    int qi0 = i0 + r0, qi1 = i0 + r1;

    const float* qbase = g_q + (((size_t)bh) * Sx + i0) * Dx;
    for (int idx = tid; idx < 1024; idx += 256) {
        int row = idx >> 4, c4 = idx & 15;
        *(float4*)&Qs[row * 68 + c4 * 4] =
            tf32r4(*(const float4*)(qbase + row * 64 + c4 * 4));
    }

    float o[8][4];
#pragma unroll
    for (int ni = 0; ni < 8; ni++)
#pragma unroll
        for (int e = 0; e < 4; e++) o[ni][e] = 0.f;
    float m0 = -1e30f, m1 = -1e30f, l0 = 0.f, l1 = 0.f;

    int ntiles = qt + 17;
    const float* kbase = g_k + ((size_t)bh) * Jx * Dx;
    const float* vbase = g_v + ((size_t)bh) * Jx * Dx;
    const float* relrow0 = rel + ((size_t)h * Sx + qi0) * Jx;
    const float* relrow1 = rel + ((size_t)h * Sx + qi1) * Jx;

    for (int t = 0; t < ntiles; t++) {
        int j0 = t * 64;
        __syncthreads();
        for (int idx = tid; idx < 1024; idx += 256) {
            int row = idx >> 4, c4 = idx & 15;
            *(float4*)&Ks[row * 68 + c4 * 4] =
                *(const float4*)(kbase + (size_t)(j0 + row) * 64 + c4 * 4);
            *(float4*)&Vs[row * 68 + c4 * 4] =
                *(const float4*)(vbase + (size_t)(j0 + row) * 64 + c4 * 4);
        }
        __syncthreads();

        float c[4][4];
#pragma unroll
        for (int ni = 0; ni < 4; ni++)
#pragma unroll
            for (int e = 0; e < 4; e++) c[ni][e] = 0.f;
#pragma unroll
        for (int kk = 0; kk < 8; kk++) {
            int kb = kk * 8;
            float a[4];
            a[0] = Qs[r0 * 68 + kb + tig];
            a[1] = Qs[r1 * 68 + kb + tig];
            a[2] = Qs[r0 * 68 + kb + tig + 4];
            a[3] = Qs[r1 * 68 + kb + tig + 4];
#pragma unroll
            for (int ni = 0; ni < 4; ni++) {
                int krow = wn * 32 + ni * 8 + g;
                float b[2];
                b[0] = Ks[krow * 68 + kb + tig];
                b[1] = Ks[krow * 68 + kb + tig + 4];
                mma_tf32(c[ni], a, b);
            }
        }

        if (t == ntiles - 1) {
#pragma unroll
            for (int ni = 0; ni < 4; ni++) {
                int kcol = wn * 32 + ni * 8 + tig * 2;
                int kj = j0 + kcol;
                float2 rp0 = *(const float2*)(relrow0 + kj);
                float2 rp1 = *(const float2*)(relrow1 + kj);
                c[ni][0] = (kj     <= qi0 + XLx) ? (c[ni][0] + rp0.x) * 0.125f : -1e30f;
                c[ni][1] = (kj + 1 <= qi0 + XLx) ? (c[ni][1] + rp0.y) * 0.125f : -1e30f;
                c[ni][2] = (kj     <= qi1 + XLx) ? (c[ni][2] + rp1.x) * 0.125f : -1e30f;
                c[ni][3] = (kj + 1 <= qi1 + XLx) ? (c[ni][3] + rp1.y) * 0.125f : -1e30f;
            }
        } else {
#pragma unroll
            for (int ni = 0; ni < 4; ni++) {
                int kcol = wn * 32 + ni * 8 + tig * 2;
                int kj = j0 + kcol;
                float2 rp0 = *(const float2*)(relrow0 + kj);
                float2 rp1 = *(const float2*)(relrow1 + kj);
                c[ni][0] = (c[ni][0] + rp0.x) * 0.125f;
                c[ni][1] = (c[ni][1] + rp0.y) * 0.125f;
                c[ni][2] = (c[ni][2] + rp1.x) * 0.125f;
                c[ni][3] = (c[ni][3] + rp1.y) * 0.125f;
            }
        }

        float rm0 = -1e30f, rm1 = -1e30f;
#pragma unroll
        for (int ni = 0; ni < 4; ni++) {
            rm0 = fmaxf(rm0, fmaxf(c[ni][0], c[ni][1]));
            rm1 = fmaxf(rm1, fmaxf(c[ni][2], c[ni][3]));
        }
        rm0 = fmaxf(rm0, __shfl_xor_sync(0xffffffffu, rm0, 1));
        rm0 = fmaxf(rm0, __shfl_xor_sync(0xffffffffu, rm0, 2));
        rm1 = fmaxf(rm1, __shfl_xor_sync(0xffffffffu, rm1, 1));
        rm1 = fmaxf(rm1, __shfl_xor_sync(0xffffffffu, rm1, 2));
        float mn0 = fmaxf(m0, rm0), mn1 = fmaxf(m1, rm1);
        float al0 = __expf(m0 - mn0), al1 = __expf(m1 - mn1);
        float ls0 = 0.f, ls1 = 0.f;
#pragma unroll
        for (int ni = 0; ni < 4; ni++) {
            int kcol = ni * 8 + tig * 2;
            float p00 = tf32r(__expf(c[ni][0] - mn0));
            float p01 = tf32r(__expf(c[ni][1] - mn0));
            float p10 = tf32r(__expf(c[ni][2] - mn1));
            float p11 = tf32r(__expf(c[ni][3] - mn1));
            ls0 += p00 + p01; ls1 += p10 + p11;
            Pw[g * 36 + kcol]           = p00;
            Pw[g * 36 + kcol + 1]       = p01;
            Pw[(g + 8) * 36 + kcol]     = p10;
            Pw[(g + 8) * 36 + kcol + 1] = p11;
        }
        ls0 += __shfl_xor_sync(0xffffffffu, ls0, 1);
        ls0 += __shfl_xor_sync(0xffffffffu, ls0, 2);
        ls1 += __shfl_xor_sync(0xffffffffu, ls1, 1);
        ls1 += __shfl_xor_sync(0xffffffffu, ls1, 2);
        l0 = l0 * al0 + ls0;
        l1 = l1 * al1 + ls1;
        m0 = mn0; m1 = mn1;
#pragma unroll
        for (int ni = 0; ni < 8; ni++) {
            o[ni][0] *= al0; o[ni][1] *= al0;
            o[ni][2] *= al1; o[ni][3] *= al1;
        }
        __syncwarp();

#pragma unroll
        for (int kk = 0; kk < 4; kk++) {
            int kb = kk * 8;
            float a[4];
            a[0] = Pw[g * 36 + kb + tig];
            a[1] = Pw[(g + 8) * 36 + kb + tig];
            a[2] = Pw[g * 36 + kb + tig + 4];
            a[3] = Pw[(g + 8) * 36 + kb + tig + 4];
            int vrow = wn * 32 + kb + tig;
#pragma unroll
            for (int ni = 0; ni < 8; ni++) {
                float b[2];
                b[0] = Vs[vrow * 68 + ni * 8 + g];
                b[1] = Vs[(vrow + 4) * 68 + ni * 8 + g];
                mma_tf32(o[ni], a, b);
            }
        }
    }

    __syncthreads();
    if (wn == 1) {
        float* M = Ks + (wm * 16) * 68;
#pragma unroll
        for (int ni = 0; ni < 8; ni++) {
            int col = ni * 8 + tig * 2;
            M[g * 68 + col]           = o[ni][0];
            M[g * 68 + col + 1]       = o[ni][1];
            M[(g + 8) * 68 + col]     = o[ni][2];
            M[(g + 8) * 68 + col + 1] = o[ni][3];
        }
        if (tig == 0) {
            Vs[r0] = m0; Vs[r1] = m1;
            Vs[64 + r0] = l0; Vs[64 + r1] = l1;
        }
    }
    __syncthreads();
    if (wn == 0) {
        float gsig = 1.f / (1.f + __expf(-gate[h]));
        float m1p0 = Vs[r0], m1p1 = Vs[r1];
        float l1p0 = Vs[64 + r0], l1p1 = Vs[64 + r1];
        float mt0 = fmaxf(m0, m1p0), mt1 = fmaxf(m1, m1p1);
        float a00 = __expf(m0 - mt0),   a01 = __expf(m1p0 - mt0);
        float a10 = __expf(m1 - mt1),   a11 = __expf(m1p1 - mt1);
        float inv0 = gsig / (l0 * a00 + l1p0 * a01);
        float inv1 = gsig / (l1 * a10 + l1p1 * a11);
        float* M = Ks + (wm * 16) * 68;
#pragma unroll
        for (int ni = 0; ni < 8; ni++) {
            int col = ni * 8 + tig * 2;
            float2 s0, s1;
            s0.x = (o[ni][0] * a00 + M[g * 68 + col]           * a01) * inv0;
            s0.y = (o[ni][1] * a00 + M[g * 68 + col + 1]       * a01) * inv0;
            s1.x = (o[ni][2] * a10 + M[(g + 8) * 68 + col]     * a11) * inv1;
            s1.y = (o[ni][3] * a10 + M[(g + 8) * 68 + col + 1] * a11) * inv1;
            *(float2*)&g_loc[(((size_t)bh) * Sx + qi0) * Dx + col] = s0;
            *(float2*)&g_loc[(((size_t)bh) * Sx + qi1) * Dx + col] = s1;
        }
    }
}

// ===========================================================================
// Output projection: out = (g_loc + g_ext) @ Wo^T + bo, 3xFP16 scaled split.
// ===========================================================================
__global__ __launch_bounds__(256) void out_gemm(const float* __restrict__ W,
                                                const float* __restrict__ bias,
                                                float* __restrict__ dst)
{
    extern __shared__ float smg[];
    uint32_t* Ah = (uint32_t*)smg;          // [128][20] words
    uint32_t* Al = Ah + 128 * 20;
    uint32_t* Bh = Al + 128 * 20;
    uint32_t* Bl = Bh + 64 * 20;

    int tid = threadIdx.x;
    int wid = tid >> 5, lane = tid & 31;
    int wm = wid & 3, wn = wid >> 2;
    int g = lane >> 2, tig = lane & 3;
    int m0 = blockIdx.x * 128, n0 = blockIdx.y * 64;

    float accM[2][4][4], accC[2][4][4];
#pragma unroll
    for (int i = 0; i < 2; i++)
#pragma unroll
        for (int j = 0; j < 4; j++)
#pragma unroll
            for (int e = 0; e < 4; e++) { accM[i][j][e] = 0.f; accC[i][j][e] = 0.f; }

    int a_row = tid >> 1;
    int a_c0  = (tid & 1) * 16;
    int b_row = tid >> 2;
    int b_c0  = (tid & 3) * 8;
    int aw0 = a_row * 20 + (a_c0 >> 1);
    int bw0 = b_row * 20 + (b_c0 >> 1);

    int mrow = m0 + a_row;
    int ab = mrow >> 10, as_ = mrow & 1023;
    const float* extp = g_ext + (size_t)mrow * 512;
    const float* Wgp = W + (size_t)(n0 + b_row) * 512 + b_c0;

    for (int kc = 0; kc < 16; kc++) {
        int k0 = kc * 32;
        float4 ra[4], rb[2];
#pragma unroll
        for (int i = 0; i < 4; i++) {
            int cc = a_c0 + k0 + i * 4;
            int hh = cc >> 6, dd = cc & 63;
            float4 f1 = *(const float4*)&g_loc[(((size_t)(ab * Hx + hh)) * Sx + as_) * Dx + dd];
            float4 f2 = *(const float4*)(extp + cc);
            ra[i].x = f1.x + f2.x; ra[i].y = f1.y + f2.y;
            ra[i].z = f1.z + f2.z; ra[i].w = f1.w + f2.w;
        }
#pragma unroll
        for (int i = 0; i < 2; i++) rb[i] = *(const float4*)(Wgp + k0 + i * 4);
        __syncthreads();
#pragma unroll
        for (int i = 0; i < 4; i++) {
            uint32_t h0, l0, h1, l1;
            split2(ra[i].x, ra[i].y, h0, l0);
            split2(ra[i].z, ra[i].w, h1, l1);
            Ah[aw0 + i * 2]     = h0;  Ah[aw0 + i * 2 + 1] = h1;
            Al[aw0 + i * 2]     = l0;  Al[aw0 + i * 2 + 1] = l1;
        }
#pragma unroll
        for (int i = 0; i < 2; i++) {
            uint32_t h0, l0, h1, l1;
            split2(rb[i].x, rb[i].y, h0, l0);
            split2(rb[i].z, rb[i].w, h1, l1);
            Bh[bw0 + i * 2]     = h0;  Bh[bw0 + i * 2 + 1] = h1;
            Bl[bw0 + i * 2]     = l0;  Bl[bw0 + i * 2 + 1] = l1;
        }
        __syncthreads();

#pragma unroll
        for (int ks = 0; ks < 2; ks++) {
            int kw = ks * 8;
            uint32_t ah[2][4], al[2][4];
#pragma unroll
            for (int mi = 0; mi < 2; mi++) {
                int base = wm * 32 + mi * 16;
                int r0w = (base + g) * 20 + kw, r1w = (base + g + 8) * 20 + kw;
                ah[mi][0] = Ah[r0w + tig];     ah[mi][1] = Ah[r1w + tig];
                ah[mi][2] = Ah[r0w + tig + 4]; ah[mi][3] = Ah[r1w + tig + 4];
                al[mi][0] = Al[r0w + tig];     al[mi][1] = Al[r1w + tig];
                al[mi][2] = Al[r0w + tig + 4]; al[mi][3] = Al[r1w + tig + 4];
            }
            uint32_t bh[4][2], bl[4][2];
#pragma unroll
            for (int ni = 0; ni < 4; ni++) {
                int nw = (wn * 32 + ni * 8 + g) * 20 + kw;
                bh[ni][0] = Bh[nw + tig]; bh[ni][1] = Bh[nw + tig + 4];
                bl[ni][0] = Bl[nw + tig]; bl[ni][1] = Bl[nw + tig + 4];
            }
#pragma unroll
            for (int mi = 0; mi < 2; mi++)
#pragma unroll
                for (int ni = 0; ni < 4; ni++) {
                    mma_f16(accM[mi][ni], ah[mi], bh[ni]);
                    mma_f16(accC[mi][ni], ah[mi], bl[ni]);
                    mma_f16(accC[mi][ni], al[mi], bh[ni]);
                }
        }
    }

#pragma unroll
    for (int mi = 0; mi < 2; mi++)
#pragma unroll
        for (int ni = 0; ni < 4; ni++)
#pragma unroll
            for (int e = 0; e < 4; e++) {
                int m = m0 + wm * 32 + mi * 16 + g + ((e >> 1) * 8);
                int n = n0 + wn * 32 + ni * 8 + tig * 2 + (e & 1);
                dst[(size_t)m * EMBx + n] =
                    accM[mi][ni][e] + accC[mi][ni][e] * RINV + bias[n];
            }
}

// ---------------------------------------------------------------------------
extern "C" void kernel_launch(void* const* d_in, const int* in_sizes, int n_in,
                              void* d_out, int out_size)
{
    (void)in_sizes; (void)n_in; (void)out_size;
    const float* x    = (const float*)d_in[0];
    const float* rel  = (const float*)d_in[1];
    const float* xlm  = (const float*)d_in[2];
    const float* knn  = (const float*)d_in[3];
    const float* Wq   = (const float*)d_in[4];
    const float* bq   = (const float*)d_in[5];
    const float* Wk   = (const float*)d_in[6];
    const float* bk   = (const float*)d_in[7];
    const float* Wv   = (const float*)d_in[8];
    const float* bv   = (const float*)d_in[9];
    const float* Wo   = (const float*)d_in[10];
    const float* bo   = (const float*)d_in[11];
    const float* gate = (const float*)d_in[12];

    float* out   = (float*)d_out;
    float* kvout = out + (size_t)Bx * Sx * EMBx;

    const int gsm = 7680 * 4;                                         // 30,720
    cudaFuncSetAttribute(qkv_gemm,
                         cudaFuncAttributeMaxDynamicSharedMemorySize, gsm);
    qkv_gemm<<<1792, 256, gsm>>>(x, Wq, bq, Wk, bk, Wv, bv, xlm, kvout);

    const int asmem = (3 * 64 * 68 + 8 * 576) * (int)sizeof(float);   // 70,656
    cudaFuncSetAttribute(attn_kernel,
                         cudaFuncAttributeMaxDynamicSharedMemorySize, asmem);
    attn_kernel<<<512, 256, asmem>>>(rel, gate);

    const int ksm = 64 * 1024;
    cudaFuncSetAttribute(knn_kernel,
                         cudaFuncAttributeMaxDynamicSharedMemorySize, ksm);
    knn_kernel<<<4096, 256, ksm>>>(gate, knn);

    cudaFuncSetAttribute(out_gemm,
                         cudaFuncAttributeMaxDynamicSharedMemorySize, gsm);
    out_gemm<<<dim3(32, 8), 256, gsm>>>(Wo, bo, out);
}

// round 12
// speedup vs baseline: 1.5373x; 1.2935x over previous
#include <cuda_runtime.h>
#include <cuda_fp16.h>
#include <cstdint>

#define Bx   4
#define Sx   1024
#define Hx   8
#define Dx   64
#define HDx  512
#define EMBx 512
#define XLx  1024
#define Jx   2048
#define KKx  32

#define RSCL 2048.0f
#define RINV 4.8828125e-4f

// ---------------- device scratch ----------------
__device__ float  g_q  [Bx * Hx * Sx * Dx];   // exact (knn reads it)
__device__ __half g_qh [Bx * Hx * Sx * Dx];   // fp16 for attention
__device__ __half g_kh [Bx * Hx * Jx * Dx];   // [bh][j][d] fp16
__device__ __half g_vt [Bx * Hx * Dx * Jx];   // [bh][d][j] fp16 (transposed)
__device__ float  g_loc[Bx * Hx * Sx * Dx];   // g * local attn out
__device__ float  g_ext[Bx * Sx * HDx];       // (1-g) * knn out

// ---------------- helpers ----------------
__device__ __forceinline__ float tf32r(float x) {
    uint32_t u;
    asm("cvt.rna.tf32.f32 %0, %1;" : "=r"(u) : "f"(x));
    return __uint_as_float(u);
}
__device__ __forceinline__ float4 tf32r4(float4 f) {
    f.x = tf32r(f.x); f.y = tf32r(f.y); f.z = tf32r(f.z); f.w = tf32r(f.w);
    return f;
}
__device__ __forceinline__ void mma_tf32(float* c, const float* a, const float* b)
{
    asm volatile(
        "mma.sync.aligned.m16n8k8.row.col.f32.tf32.tf32.f32 "
        "{%0,%1,%2,%3},{%4,%5,%6,%7},{%8,%9},{%0,%1,%2,%3};\n"
        : "+f"(c[0]), "+f"(c[1]), "+f"(c[2]), "+f"(c[3])
        : "r"(__float_as_uint(a[0])), "r"(__float_as_uint(a[1])),
          "r"(__float_as_uint(a[2])), "r"(__float_as_uint(a[3])),
          "r"(__float_as_uint(b[0])), "r"(__float_as_uint(b[1])));
}
__device__ __forceinline__ void mma_f16(float* c, const uint32_t* a, const uint32_t* b)
{
    asm volatile(
        "mma.sync.aligned.m16n8k16.row.col.f32.f16.f16.f32 "
        "{%0,%1,%2,%3},{%4,%5,%6,%7},{%8,%9},{%0,%1,%2,%3};\n"
        : "+f"(c[0]), "+f"(c[1]), "+f"(c[2]), "+f"(c[3])
        : "r"(a[0]), "r"(a[1]), "r"(a[2]), "r"(a[3]),
          "r"(b[0]), "r"(b[1]));
}
__device__ __forceinline__ void split2(float x, float y, uint32_t& hi, uint32_t& lo)
{
    __half hx = __float2half_rn(x), hy = __float2half_rn(y);
    float rx = (x - __half2float(hx)) * RSCL;
    float ry = (y - __half2float(hy)) * RSCL;
    __half2 h2 = __halves2half2(hx, hy);
    __half2 l2 = __halves2half2(__float2half_rn(rx), __float2half_rn(ry));
    hi = *(uint32_t*)&h2;
    lo = *(uint32_t*)&l2;
}

// ===========================================================================
// Fused QKV projection GEMM (+ xl_memory copy blocks).
// nsec 0 (Q): 1xTF32; writes g_q (float) and g_qh (half).
// nsec 1 (K): 3xFP16 split; writes g_kh (half) + kvout (exact).
// nsec 2 (V): 3xFP16 split; writes g_vt (half, transposed) + kvout (exact).
// ===========================================================================
__global__ __launch_bounds__(256) void qkv_gemm(
    const float* __restrict__ x,
    const float* __restrict__ Wq, const float* __restrict__ bq,
    const float* __restrict__ Wk, const float* __restrict__ bk,
    const float* __restrict__ Wv, const float* __restrict__ bv,
    const float* __restrict__ xlm,
    float* __restrict__ kvout)
{
    extern __shared__ float smg[];

    if (blockIdx.x >= 768) {
        int base = (blockIdx.x - 768) * 1024;
#pragma unroll
        for (int i = 0; i < 4; i++) {
            int idx = base + i * 256 + threadIdx.x;
            int n4 = idx & 127;
            int rest = idx >> 7;
            int c = rest & 1;  rest >>= 1;
            int j = rest & 1023;
            int b = rest >> 10;
            float4 f = ((const float4*)xlm)[idx];
            int n = n4 * 4;
            int h = n >> 6, d = n & 63;
            int bh = b * Hx + h;
            if (c == 0) {
                __half2 p0 = __floats2half2_rn(f.x, f.y);
                __half2 p1 = __floats2half2_rn(f.z, f.w);
                __half* dst = g_kh + ((size_t)bh * Jx + j) * Dx + d;
                *(__half2*)dst = p0;
                *(__half2*)(dst + 2) = p1;
            } else {
                __half* dst = g_vt + ((size_t)bh * Dx + d) * Jx + j;
                dst[0]      = __float2half_rn(f.x);
                dst[Jx]     = __float2half_rn(f.y);
                dst[2 * Jx] = __float2half_rn(f.z);
                dst[3 * Jx] = __float2half_rn(f.w);
            }
        }
        return;
    }

    int bm   = blockIdx.x & 31;
    int nbi  = blockIdx.x >> 5;
    int nsec = nbi >> 3;
    int m0 = bm * 128, n0 = (nbi & 7) * 64;

    const float* W    = (nsec == 0) ? Wq : (nsec == 1) ? Wk : Wv;
    const float* bias = (nsec == 0) ? bq : (nsec == 1) ? bk : bv;

    int tid = threadIdx.x;
    int wid = tid >> 5, lane = tid & 31;
    int wm = wid & 3, wn = wid >> 2;
    int g = lane >> 2, tig = lane & 3;

    int a_row = tid >> 1;
    int a_c0  = (tid & 1) * 16;
    int b_row = tid >> 2;
    int b_c0  = (tid & 3) * 8;

    const float* Agp = x + (size_t)(m0 + a_row) * 512 + a_c0;
    const float* Wgp = W + (size_t)(n0 + b_row) * 512 + b_c0;

    if (nsec == 0) {
        float* Ab = smg;
        float* Bb = Ab + 128 * 36;

        float acc[2][4][4];
#pragma unroll
        for (int i = 0; i < 2; i++)
#pragma unroll
            for (int j = 0; j < 4; j++)
#pragma unroll
                for (int e = 0; e < 4; e++) acc[i][j][e] = 0.f;

        for (int kc = 0; kc < 16; kc++) {
            int k0 = kc * 32;
            float4 ra[4], rb[2];
#pragma unroll
            for (int i = 0; i < 4; i++) ra[i] = *(const float4*)(Agp + k0 + i * 4);
#pragma unroll
            for (int i = 0; i < 2; i++) rb[i] = *(const float4*)(Wgp + k0 + i * 4);
            __syncthreads();
#pragma unroll
            for (int i = 0; i < 4; i++)
                *(float4*)&Ab[a_row * 36 + a_c0 + i * 4] = tf32r4(ra[i]);
#pragma unroll
            for (int i = 0; i < 2; i++)
                *(float4*)&Bb[b_row * 36 + b_c0 + i * 4] = tf32r4(rb[i]);
            __syncthreads();

#pragma unroll
            for (int kk = 0; kk < 4; kk++) {
                int kb = kk * 8;
                float a[2][4];
#pragma unroll
                for (int mi = 0; mi < 2; mi++) {
                    int base = wm * 32 + mi * 16;
                    a[mi][0] = Ab[(base + g)     * 36 + kb + tig];
                    a[mi][1] = Ab[(base + g + 8) * 36 + kb + tig];
                    a[mi][2] = Ab[(base + g)     * 36 + kb + tig + 4];
                    a[mi][3] = Ab[(base + g + 8) * 36 + kb + tig + 4];
                }
                float b[4][2];
#pragma unroll
                for (int ni = 0; ni < 4; ni++) {
                    int nb = wn * 32 + ni * 8;
                    b[ni][0] = Bb[(nb + g) * 36 + kb + tig];
                    b[ni][1] = Bb[(nb + g) * 36 + kb + tig + 4];
                }
#pragma unroll
                for (int mi = 0; mi < 2; mi++)
#pragma unroll
                    for (int ni = 0; ni < 4; ni++)
                        mma_tf32(acc[mi][ni], a[mi], b[ni]);
            }
        }

#pragma unroll
        for (int mi = 0; mi < 2; mi++)
#pragma unroll
            for (int ni = 0; ni < 4; ni++)
#pragma unroll
                for (int e = 0; e < 4; e++) {
                    int m = m0 + wm * 32 + mi * 16 + g + ((e >> 1) * 8);
                    int n = n0 + wn * 32 + ni * 8 + tig * 2 + (e & 1);
                    float c = acc[mi][ni][e] + bias[n];
                    int b = m >> 10, s = m & 1023;
                    int h = n >> 6, d = n & 63;
                    size_t qi = (((size_t)(b * Hx + h)) * Sx + s) * Dx + d;
                    g_q[qi]  = c;
                    g_qh[qi] = __float2half_rn(c);
                }
        return;
    }

    // ---------------- K/V: 3xFP16 scaled-residual path ----------------
    uint32_t* Ah = (uint32_t*)smg;
    uint32_t* Al = Ah + 128 * 20;
    uint32_t* Bh = Al + 128 * 20;
    uint32_t* Bl = Bh + 64 * 20;

    float accM[2][4][4], accC[2][4][4];
#pragma unroll
    for (int i = 0; i < 2; i++)
#pragma unroll
        for (int j = 0; j < 4; j++)
#pragma unroll
            for (int e = 0; e < 4; e++) { accM[i][j][e] = 0.f; accC[i][j][e] = 0.f; }

    int aw0 = a_row * 20 + (a_c0 >> 1);
    int bw0 = b_row * 20 + (b_c0 >> 1);

    for (int kc = 0; kc < 16; kc++) {
        int k0 = kc * 32;
        float4 ra[4], rb[2];
#pragma unroll
        for (int i = 0; i < 4; i++) ra[i] = *(const float4*)(Agp + k0 + i * 4);
#pragma unroll
        for (int i = 0; i < 2; i++) rb[i] = *(const float4*)(Wgp + k0 + i * 4);
        __syncthreads();
#pragma unroll
        for (int i = 0; i < 4; i++) {
            uint32_t h0, l0, h1, l1;
            split2(ra[i].x, ra[i].y, h0, l0);
            split2(ra[i].z, ra[i].w, h1, l1);
            Ah[aw0 + i * 2]     = h0;  Ah[aw0 + i * 2 + 1] = h1;
            Al[aw0 + i * 2]     = l0;  Al[aw0 + i * 2 + 1] = l1;
        }
#pragma unroll
        for (int i = 0; i < 2; i++) {
            uint32_t h0, l0, h1, l1;
            split2(rb[i].x, rb[i].y, h0, l0);
            split2(rb[i].z, rb[i].w, h1, l1);
            Bh[bw0 + i * 2]     = h0;  Bh[bw0 + i * 2 + 1] = h1;
            Bl[bw0 + i * 2]     = l0;  Bl[bw0 + i * 2 + 1] = l1;
        }
        __syncthreads();

#pragma unroll
        for (int ks = 0; ks < 2; ks++) {
            int kw = ks * 8;
            uint32_t ah[2][4], al[2][4];
#pragma unroll
            for (int mi = 0; mi < 2; mi++) {
                int base = wm * 32 + mi * 16;
                int r0w = (base + g) * 20 + kw, r1w = (base + g + 8) * 20 + kw;
                ah[mi][0] = Ah[r0w + tig];     ah[mi][1] = Ah[r1w + tig];
                ah[mi][2] = Ah[r0w + tig + 4]; ah[mi][3] = Ah[r1w + tig + 4];
                al[mi][0] = Al[r0w + tig];     al[mi][1] = Al[r1w + tig];
                al[mi][2] = Al[r0w + tig + 4]; al[mi][3] = Al[r1w + tig + 4];
            }
            uint32_t bh[4][2], bl[4][2];
#pragma unroll
            for (int ni = 0; ni < 4; ni++) {
                int nw = (wn * 32 + ni * 8 + g) * 20 + kw;
                bh[ni][0] = Bh[nw + tig]; bh[ni][1] = Bh[nw + tig + 4];
                bl[ni][0] = Bl[nw + tig]; bl[ni][1] = Bl[nw + tig + 4];
            }
#pragma unroll
            for (int mi = 0; mi < 2; mi++)
#pragma unroll
                for (int ni = 0; ni < 4; ni++) {
                    mma_f16(accM[mi][ni], ah[mi], bh[ni]);
                    mma_f16(accC[mi][ni], ah[mi], bl[ni]);
                    mma_f16(accC[mi][ni], al[mi], bh[ni]);
                }
        }
    }

#pragma unroll
    for (int mi = 0; mi < 2; mi++)
#pragma unroll
        for (int ni = 0; ni < 4; ni++)
#pragma unroll
            for (int e = 0; e < 4; e++) {
                int m = m0 + wm * 32 + mi * 16 + g + ((e >> 1) * 8);
                int n = n0 + wn * 32 + ni * 8 + tig * 2 + (e & 1);
                float c = accM[mi][ni][e] + accC[mi][ni][e] * RINV + bias[n];
                int b = m >> 10, s = m & 1023;
                int h = n >> 6, d = n & 63;
                int bh = b * Hx + h;
                if (nsec == 1) {
                    g_kh[((size_t)bh * Jx + XLx + s) * Dx + d] = __float2half_rn(c);
                    kvout[(((size_t)(b * Sx + s)) * 2 + 0) * HDx + n] = c;
                } else {
                    g_vt[((size_t)bh * Dx + d) * Jx + XLx + s] = __float2half_rn(c);
                    kvout[(((size_t)(b * Sx + s)) * 2 + 1) * HDx + n] = c;
                }
            }
}

// ===========================================================================
// kNN attention (unchanged).
// ===========================================================================
__global__ __launch_bounds__(256) void knn_kernel(const float* __restrict__ gate,
                                                  const float* __restrict__ knn)
{
    extern __shared__ float sm[];
    int tid = threadIdx.x;
    int wid = tid >> 5, lane = tid & 31;

    int b = blockIdx.x >> 10, s = blockIdx.x & 1023;
    int h = wid;

    const float* qp = g_q + (((size_t)(b * Hx + h)) * Sx + s) * Dx;
    float2 qv = *(const float2*)(qp + lane * 2);

    const float4* src =
        (const float4*)(knn + ((size_t)(b * Sx + s)) * (KKx * 2 * HDx));
    float4* dstv = (float4*)sm;

    float m = -1e30f, l = 0.f, a0 = 0.f, a1 = 0.f;

#pragma unroll
    for (int c = 0; c < 2; c++) {
        __syncthreads();
#pragma unroll
        for (int i = 0; i < 16; i++) {
            int idx = tid + i * 256;
            dstv[idx] = src[c * 4096 + idx];
        }
        __syncthreads();

        float sc[16];
#pragma unroll
        for (int kk = 0; kk < 16; kk++) {
            float2 kf = *(const float2*)(sm + kk * 1024 + h * 64 + lane * 2);
            float p = qv.x * kf.x + qv.y * kf.y;
            p += __shfl_xor_sync(0xffffffffu, p, 16);
            p += __shfl_xor_sync(0xffffffffu, p, 8);
            p += __shfl_xor_sync(0xffffffffu, p, 4);
            p += __shfl_xor_sync(0xffffffffu, p, 2);
            p += __shfl_xor_sync(0xffffffffu, p, 1);
            sc[kk] = p * 0.125f;
        }
        float cm = sc[0];
#pragma unroll
        for (int kk = 1; kk < 16; kk++) cm = fmaxf(cm, sc[kk]);
        float mn = fmaxf(m, cm);
        float al = __expf(m - mn);
        a0 *= al; a1 *= al; l *= al;
#pragma unroll
        for (int kk = 0; kk < 16; kk++) {
            float p = __expf(sc[kk] - mn);
            l += p;
            float2 vf = *(const float2*)(sm + kk * 1024 + 512 + h * 64 + lane * 2);
            a0 = fmaf(p, vf.x, a0);
            a1 = fmaf(p, vf.y, a1);
        }
        m = mn;
    }

    float gg = 1.f / (1.f + __expf(-gate[h]));
    float w = (1.f - gg) / l;
    float2 st; st.x = w * a0; st.y = w * a1;
    *(float2*)&g_ext[((size_t)(b * Sx + s)) * HDx + h * 64 + lane * 2] = st;
}

// ===========================================================================
// Local causal XL attention — fp16 m16n8k16 tensor path.
// smem: Qs2[64][36] + Ks2[64][36] + Vt2[64][36] (half2 words) + Pw2 8x[16][20]
// ===========================================================================
__global__ __launch_bounds__(256) void attn_kernel(const float* __restrict__ rel,
                                                   const float* __restrict__ gate)
{
    extern __shared__ uint32_t smw[];
    uint32_t* Qs2 = smw;                    // [64][36] half2 words
    uint32_t* Ks2 = Qs2 + 64 * 36;          // [64][36]
    uint32_t* Vt2 = Ks2 + 64 * 36;          // [64][36] (row = d, col = key word)
    int tid = threadIdx.x;
    int wid = tid >> 5, lane = tid & 31;
    uint32_t* Pw2 = Vt2 + 64 * 36 + wid * 320;  // per-warp [16][20]

    int bh = blockIdx.x >> 4;
    int h = bh & 7;
    int qt = 15 - (blockIdx.x & 15);
    int i0 = qt * 64;
    int wm = wid & 3, wn = wid >> 2;
    int g = lane >> 2, tig = lane & 3;
    int r0 = wm * 16 + g, r1 = r0 + 8;
    int qi0 = i0 + r0, qi1 = i0 + r1;

    // load Q tile (half, 64x64): 512 uint4; 2 per thread
    {
        const uint4* qsrc = (const uint4*)(g_qh + (((size_t)bh) * Sx + i0) * Dx);
#pragma unroll
        for (int i = 0; i < 2; i++) {
            int idx = tid + i * 256;
            int row = idx >> 3, cw = (idx & 7) * 4;
            *(uint4*)&Qs2[row * 36 + cw] = qsrc[idx];
        }
    }

    float o[8][4];
#pragma unroll
    for (int ni = 0; ni < 8; ni++)
#pragma unroll
        for (int e = 0; e < 4; e++) o[ni][e] = 0.f;
    float m0 = -1e30f, m1 = -1e30f, l0 = 0.f, l1 = 0.f;

    int ntiles = qt + 17;
    const __half* kbase = g_kh + ((size_t)bh) * Jx * Dx;
    const __half* vbase = g_vt + ((size_t)bh) * Dx * Jx;
    const float* relrow0 = rel + ((size_t)h * Sx + qi0) * Jx;
    const float* relrow1 = rel + ((size_t)h * Sx + qi1) * Jx;

    for (int t = 0; t < ntiles; t++) {
        int j0 = t * 64;
        __syncthreads();
        // K tile: rows=key, 64x64 half; V tile: rows=d, cols=key
#pragma unroll
        for (int i = 0; i < 2; i++) {
            int idx = tid + i * 256;
            int row = idx >> 3, cw = (idx & 7) * 4;
            *(uint4*)&Ks2[row * 36 + cw] =
                *(const uint4*)(kbase + (size_t)(j0 + row) * Dx + cw * 2);
            *(uint4*)&Vt2[row * 36 + cw] =
                *(const uint4*)(vbase + (size_t)row * Jx + j0 + cw * 2);
        }
        __syncthreads();

        // ---- S = Q K^T (fp16, k=64 -> 4 k16 steps) ----
        float c[4][4];
#pragma unroll
        for (int ni = 0; ni < 4; ni++)
#pragma unroll
            for (int e = 0; e < 4; e++) c[ni][e] = 0.f;
#pragma unroll
        for (int kk = 0; kk < 4; kk++) {
            int kw = kk * 8;
            uint32_t a[4];
            a[0] = Qs2[r0 * 36 + kw + tig];
            a[1] = Qs2[r1 * 36 + kw + tig];
            a[2] = Qs2[r0 * 36 + kw + tig + 4];
            a[3] = Qs2[r1 * 36 + kw + tig + 4];
#pragma unroll
            for (int ni = 0; ni < 4; ni++) {
                int krow = wn * 32 + ni * 8 + g;
                uint32_t b[2];
                b[0] = Ks2[krow * 36 + kw + tig];
                b[1] = Ks2[krow * 36 + kw + tig + 4];
                mma_f16(c[ni], a, b);
            }
        }

        if (t == ntiles - 1) {
#pragma unroll
            for (int ni = 0; ni < 4; ni++) {
                int kcol = wn * 32 + ni * 8 + tig * 2;
                int kj = j0 + kcol;
                float2 rp0 = *(const float2*)(relrow0 + kj);
                float2 rp1 = *(const float2*)(relrow1 + kj);
                c[ni][0] = (kj     <= qi0 + XLx) ? (c[ni][0] + rp0.x) * 0.125f : -1e30f;
                c[ni][1] = (kj + 1 <= qi0 + XLx) ? (c[ni][1] + rp0.y) * 0.125f : -1e30f;
                c[ni][2] = (kj     <= qi1 + XLx) ? (c[ni][2] + rp1.x) * 0.125f : -1e30f;
                c[ni][3] = (kj + 1 <= qi1 + XLx) ? (c[ni][3] + rp1.y) * 0.125f : -1e30f;
            }
        } else {
#pragma unroll
            for (int ni = 0; ni < 4; ni++) {
                int kcol = wn * 32 + ni * 8 + tig * 2;
                int kj = j0 + kcol;
                float2 rp0 = *(const float2*)(relrow0 + kj);
                float2 rp1 = *(const float2*)(relrow1 + kj);
                c[ni][0] = (c[ni][0] + rp0.x) * 0.125f;
                c[ni][1] = (c[ni][1] + rp0.y) * 0.125f;
                c[ni][2] = (c[ni][2] + rp1.x) * 0.125f;
                c[ni][3] = (c[ni][3] + rp1.y) * 0.125f;
            }
        }

        float rm0 = -1e30f, rm1 = -1e30f;
#pragma unroll
        for (int ni = 0; ni < 4; ni++) {
            rm0 = fmaxf(rm0, fmaxf(c[ni][0], c[ni][1]));
            rm1 = fmaxf(rm1, fmaxf(c[ni][2], c[ni][3]));
        }
        rm0 = fmaxf(rm0, __shfl_xor_sync(0xffffffffu, rm0, 1));
        rm0 = fmaxf(rm0, __shfl_xor_sync(0xffffffffu, rm0, 2));
        rm1 = fmaxf(rm1, __shfl_xor_sync(0xffffffffu, rm1, 1));
        rm1 = fmaxf(rm1, __shfl_xor_sync(0xffffffffu, rm1, 2));
        float mn0 = fmaxf(m0, rm0), mn1 = fmaxf(m1, rm1);
        float al0 = __expf(m0 - mn0), al1 = __expf(m1 - mn1);
        float ls0 = 0.f, ls1 = 0.f;
#pragma unroll
        for (int ni = 0; ni < 4; ni++) {
            int kwrd = ni * 4 + tig;          // key word within warp's 32-key half
            float p00 = __expf(c[ni][0] - mn0);
            float p01 = __expf(c[ni][1] - mn0);
            float p10 = __expf(c[ni][2] - mn1);
            float p11 = __expf(c[ni][3] - mn1);
            ls0 += p00 + p01; ls1 += p10 + p11;
            __half2 hp0 = __floats2half2_rn(p00, p01);
            __half2 hp1 = __floats2half2_rn(p10, p11);
            Pw2[g * 20 + kwrd]       = *(uint32_t*)&hp0;
            Pw2[(g + 8) * 20 + kwrd] = *(uint32_t*)&hp1;
        }
        ls0 += __shfl_xor_sync(0xffffffffu, ls0, 1);
        ls0 += __shfl_xor_sync(0xffffffffu, ls0, 2);
        ls1 += __shfl_xor_sync(0xffffffffu, ls1, 1);
        ls1 += __shfl_xor_sync(0xffffffffu, ls1, 2);
        l0 = l0 * al0 + ls0;
        l1 = l1 * al1 + ls1;
        m0 = mn0; m1 = mn1;
#pragma unroll
        for (int ni = 0; ni < 8; ni++) {
            o[ni][0] *= al0; o[ni][1] *= al0;
            o[ni][2] *= al1; o[ni][3] *= al1;
        }
        __syncwarp();

        // ---- O += P V (fp16, k=32 keys -> 2 k16 steps, n = 64 dims) ----
#pragma unroll
        for (int ks = 0; ks < 2; ks++) {
            int kw = ks * 8;
            uint32_t a[4];
            a[0] = Pw2[g * 20 + kw + tig];
            a[1] = Pw2[(g + 8) * 20 + kw + tig];
            a[2] = Pw2[g * 20 + kw + tig + 4];
            a[3] = Pw2[(g + 8) * 20 + kw + tig + 4];
            int kwb = wn * 16 + kw;           // key-word offset in V tile
#pragma unroll
            for (int ni = 0; ni < 8; ni++) {
                int drow = ni * 8 + g;
                uint32_t b[2];
                b[0] = Vt2[drow * 36 + kwb + tig];
                b[1] = Vt2[drow * 36 + kwb + tig + 4];
                mma_f16(o[ni], a, b);
            }
        }
    }

    // ---- merge the two key-halves (float scratch over Ks2/Vt2; m/l in Qs2) ----
    __syncthreads();
    float* M = (float*)Ks2;                 // [64][68] floats fits in Ks2+Vt2
    float* S = (float*)Qs2;                 // m/l staging
    if (wn == 1) {
#pragma unroll
        for (int ni = 0; ni < 8; ni++) {
            int col = ni * 8 + tig * 2;
            M[r0 * 68 + col]     = o[ni][0];
            M[r0 * 68 + col + 1] = o[ni][1];
            M[r1 * 68 + col]     = o[ni][2];
            M[r1 * 68 + col + 1] = o[ni][3];
        }
        if (tig == 0) {
            S[r0] = m0; S[r1] = m1;
            S[64 + r0] = l0; S[64 + r1] = l1;
        }
    }
    __syncthreads();
    if (wn == 0) {
        float gsig = 1.f / (1.f + __expf(-gate[h]));
        float m1p0 = S[r0], m1p1 = S[r1];
        float l1p0 = S[64 + r0], l1p1 = S[64 + r1];
        float mt0 = fmaxf(m0, m1p0), mt1 = fmaxf(m1, m1p1);
        float a00 = __expf(m0 - mt0),   a01 = __expf(m1p0 - mt0);
        float a10 = __expf(m1 - mt1),   a11 = __expf(m1p1 - mt1);
        float inv0 = gsig / (l0 * a00 + l1p0 * a01);
        float inv1 = gsig / (l1 * a10 + l1p1 * a11);
#pragma unroll
        for (int ni = 0; ni < 8; ni++) {
            int col = ni * 8 + tig * 2;
            float2 s0, s1;
            s0.x = (o[ni][0] * a00 + M[r0 * 68 + col]     * a01) * inv0;
            s0.y = (o[ni][1] * a00 + M[r0 * 68 + col + 1] * a01) * inv0;
            s1.x = (o[ni][2] * a10 + M[r1 * 68 + col]     * a11) * inv1;
            s1.y = (o[ni][3] * a10 + M[r1 * 68 + col + 1] * a11) * inv1;
            *(float2*)&g_loc[(((size_t)bh) * Sx + qi0) * Dx + col] = s0;
            *(float2*)&g_loc[(((size_t)bh) * Sx + qi1) * Dx + col] = s1;
        }
    }
}

// ===========================================================================
// Output projection: out = (g_loc + g_ext) @ Wo^T + bo, 3xFP16 scaled split.
// ===========================================================================
__global__ __launch_bounds__(256) void out_gemm(const float* __restrict__ W,
                                                const float* __restrict__ bias,
                                                float* __restrict__ dst)
{
    extern __shared__ float smg[];
    uint32_t* Ah = (uint32_t*)smg;
    uint32_t* Al = Ah + 128 * 20;
    uint32_t* Bh = Al + 128 * 20;
    uint32_t* Bl = Bh + 64 * 20;

    int tid = threadIdx.x;
    int wid = tid >> 5, lane = tid & 31;
    int wm = wid & 3, wn = wid >> 2;
    int g = lane >> 2, tig = lane & 3;
    int m0 = blockIdx.x * 128, n0 = blockIdx.y * 64;

    float accM[2][4][4], accC[2][4][4];
#pragma unroll
    for (int i = 0; i < 2; i++)
#pragma unroll
        for (int j = 0; j < 4; j++)
#pragma unroll
            for (int e = 0; e < 4; e++) { accM[i][j][e] = 0.f; accC[i][j][e] = 0.f; }

    int a_row = tid >> 1;
    int a_c0  = (tid & 1) * 16;
    int b_row = tid >> 2;
    int b_c0  = (tid & 3) * 8;
    int aw0 = a_row * 20 + (a_c0 >> 1);
    int bw0 = b_row * 20 + (b_c0 >> 1);

    int mrow = m0 + a_row;
    int ab = mrow >> 10, as_ = mrow & 1023;
    const float* extp = g_ext + (size_t)mrow * 512;
    const float* Wgp = W + (size_t)(n0 + b_row) * 512 + b_c0;

    for (int kc = 0; kc < 16; kc++) {
        int k0 = kc * 32;
        float4 ra[4], rb[2];
#pragma unroll
        for (int i = 0; i < 4; i++) {
            int cc = a_c0 + k0 + i * 4;
            int hh = cc >> 6, dd = cc & 63;
            float4 f1 = *(const float4*)&g_loc[(((size_t)(ab * Hx + hh)) * Sx + as_) * Dx + dd];
            float4 f2 = *(const float4*)(extp + cc);
            ra[i].x = f1.x + f2.x; ra[i].y = f1.y + f2.y;
            ra[i].z = f1.z + f2.z; ra[i].w = f1.w + f2.w;
        }
#pragma unroll
        for (int i = 0; i < 2; i++) rb[i] = *(const float4*)(Wgp + k0 + i * 4);
        __syncthreads();
#pragma unroll
        for (int i = 0; i < 4; i++) {
            uint32_t h0, l0, h1, l1;
            split2(ra[i].x, ra[i].y, h0, l0);
            split2(ra[i].z, ra[i].w, h1, l1);
            Ah[aw0 + i * 2]     = h0;  Ah[aw0 + i * 2 + 1] = h1;
            Al[aw0 + i * 2]     = l0;  Al[aw0 + i * 2 + 1] = l1;
        }
#pragma unroll
        for (int i = 0; i < 2; i++) {
            uint32_t h0, l0, h1, l1;
            split2(rb[i].x, rb[i].y, h0, l0);
            split2(rb[i].z, rb[i].w, h1, l1);
            Bh[bw0 + i * 2]     = h0;  Bh[bw0 + i * 2 + 1] = h1;
            Bl[bw0 + i * 2]     = l0;  Bl[bw0 + i * 2 + 1] = l1;
        }
        __syncthreads();

#pragma unroll
        for (int ks = 0; ks < 2; ks++) {
            int kw = ks * 8;
            uint32_t ah[2][4], al[2][4];
#pragma unroll
            for (int mi = 0; mi < 2; mi++) {
                int base = wm * 32 + mi * 16;
                int r0w = (base + g) * 20 + kw, r1w = (base + g + 8) * 20 + kw;
                ah[mi][0] = Ah[r0w + tig];     ah[mi][1] = Ah[r1w + tig];
                ah[mi][2] = Ah[r0w + tig + 4]; ah[mi][3] = Ah[r1w + tig + 4];
                al[mi][0] = Al[r0w + tig];     al[mi][1] = Al[r1w + tig];
                al[mi][2] = Al[r0w + tig + 4]; al[mi][3] = Al[r1w + tig + 4];
            }
            uint32_t bh[4][2], bl[4][2];
#pragma unroll
            for (int ni = 0; ni < 4; ni++) {
                int nw = (wn * 32 + ni * 8 + g) * 20 + kw;
                bh[ni][0] = Bh[nw + tig]; bh[ni][1] = Bh[nw + tig + 4];
                bl[ni][0] = Bl[nw + tig]; bl[ni][1] = Bl[nw + tig + 4];
            }
#pragma unroll
            for (int mi = 0; mi < 2; mi++)
#pragma unroll
                for (int ni = 0; ni < 4; ni++) {
                    mma_f16(accM[mi][ni], ah[mi], bh[ni]);
                    mma_f16(accC[mi][ni], ah[mi], bl[ni]);
                    mma_f16(accC[mi][ni], al[mi], bh[ni]);
                }
        }
    }

#pragma unroll
    for (int mi = 0; mi < 2; mi++)
#pragma unroll
        for (int ni = 0; ni < 4; ni++)
#pragma unroll
            for (int e = 0; e < 4; e++) {
                int m = m0 + wm * 32 + mi * 16 + g + ((e >> 1) * 8);
                int n = n0 + wn * 32 + ni * 8 + tig * 2 + (e & 1);
                dst[(size_t)m * EMBx + n] =
                    accM[mi][ni][e] + accC[mi][ni][e] * RINV + bias[n];
            }
}

// ---------------------------------------------------------------------------
extern "C" void kernel_launch(void* const* d_in, const int* in_sizes, int n_in,
                              void* d_out, int out_size)
{
    (void)in_sizes; (void)n_in; (void)out_size;
    const float* x    = (const float*)d_in[0];
    const float* rel  = (const float*)d_in[1];
    const float* xlm  = (const float*)d_in[2];
    const float* knn  = (const float*)d_in[3];
    const float* Wq   = (const float*)d_in[4];
    const float* bq   = (const float*)d_in[5];
    const float* Wk   = (const float*)d_in[6];
    const float* bk   = (const float*)d_in[7];
    const float* Wv   = (const float*)d_in[8];
    const float* bv   = (const float*)d_in[9];
    const float* Wo   = (const float*)d_in[10];
    const float* bo   = (const float*)d_in[11];
    const float* gate = (const float*)d_in[12];

    float* out   = (float*)d_out;
    float* kvout = out + (size_t)Bx * Sx * EMBx;

    const int gsm = 30720;
    cudaFuncSetAttribute(qkv_gemm,
                         cudaFuncAttributeMaxDynamicSharedMemorySize, gsm);
    qkv_gemm<<<1792, 256, gsm>>>(x, Wq, bq, Wk, bk, Wv, bv, xlm, kvout);

    // 3*64*36 + 8*320 = 9472 words = 37,888 B
    const int asmem = (3 * 64 * 36 + 8 * 320) * 4;
    cudaFuncSetAttribute(attn_kernel,
                         cudaFuncAttributeMaxDynamicSharedMemorySize, asmem);
    attn_kernel<<<512, 256, asmem>>>(rel, gate);

    const int ksm = 64 * 1024;
    cudaFuncSetAttribute(knn_kernel,
                         cudaFuncAttributeMaxDynamicSharedMemorySize, ksm);
    knn_kernel<<<4096, 256, ksm>>>(gate, knn);

    cudaFuncSetAttribute(out_gemm,
                         cudaFuncAttributeMaxDynamicSharedMemorySize, gsm);
    out_gemm<<<dim3(32, 8), 256, gsm>>>(Wo, bo, out);
}